// round 1
// baseline (speedup 1.0000x reference)
#include <cuda_runtime.h>
#include <math.h>

#define NNODES 50000
#define NEDGES 800000
#define DIM    128
#define NREL   86
#define NBATCH 2048

// ---------------- scratch (device globals; no allocation allowed) ------------
__device__ float g_h  [NNODES * DIM];
__device__ float g_x1 [NNODES * DIM];
__device__ float g_x2 [NNODES * DIM];
__device__ float g_dinv[NNODES];
__device__ int   g_cnt [NNODES];
__device__ int   g_rowptr[NNODES + 1];
__device__ int   g_cur [NNODES];
__device__ int   g_col [NEDGES];
__device__ float g_T   [NREL * DIM * DIM];
__device__ float g_S   [NREL * DIM * DIM];
__device__ float g_head[NBATCH * DIM];
__device__ float g_tail[NBATCH * DIM];

// ---------------- CSR build --------------------------------------------------
__global__ void zero_cnt_kernel(int* cnt, int n) {
    int i = blockIdx.x * blockDim.x + threadIdx.x;
    if (i < n) cnt[i] = 0;
}

__global__ void count_kernel(const int* __restrict__ dst, int* cnt, int e) {
    int i = blockIdx.x * blockDim.x + threadIdx.x;
    if (i < e) atomicAdd(&cnt[dst[i]], 1);
}

// single-block exclusive scan over 50000 counts; also dinv + cursor init
__global__ void scan_kernel(const int* __restrict__ cnt, int* rowptr, int* cur,
                            float* dinv, int n) {
    __shared__ int ssum[1024];
    int t = threadIdx.x;
    int chunk = (n + 1023) / 1024;
    int beg = t * chunk;
    int end = min(beg + chunk, n);
    int s = 0;
    for (int i = beg; i < end; i++) s += cnt[i];
    ssum[t] = s;
    __syncthreads();
    // inclusive Hillis-Steele scan
    for (int off = 1; off < 1024; off <<= 1) {
        int v = (t >= off) ? ssum[t - off] : 0;
        __syncthreads();
        ssum[t] += v;
        __syncthreads();
    }
    int base = (t == 0) ? 0 : ssum[t - 1];
    for (int i = beg; i < end; i++) {
        rowptr[i] = base;
        cur[i] = base;
        dinv[i] = rsqrtf((float)(cnt[i] + 1)); // +1 self-loop
        base += cnt[i];
    }
    if (t == 1023) rowptr[n] = ssum[1023];
}

__global__ void fill_kernel(const int* __restrict__ src, const int* __restrict__ dst,
                            int* cur, int* col, int e) {
    int i = blockIdx.x * blockDim.x + threadIdx.x;
    if (i < e) {
        int d = dst[i];
        int p = atomicAdd(&cur[d], 1);
        col[p] = src[i];
    }
}

// ---------------- generic 128x128 GEMM: C = (A @ op(B)) * rowscale -----------
// A: [rows,128] (batched via strides), B: [128,128] (or transposed),
// 256 threads, 64 rows per block, 4x8 register micro-tile.
#define GTM 64
#define BS_STRIDE 132
#define AS_STRIDE 132

__global__ void gemm128_kernel(const float* __restrict__ A, long strideA,
                               const float* __restrict__ B, long strideB,
                               float* __restrict__ C, long strideC,
                               int rows, int transB,
                               const float* __restrict__ rowscale) {
    extern __shared__ float sm[];
    float* Bs = sm;                      // 128 x 132
    float* As = sm + 128 * BS_STRIDE;    // 64 x 132

    int batch = blockIdx.y;
    A += (long)batch * strideA;
    B += (long)batch * strideB;
    C += (long)batch * strideC;

    int row0 = blockIdx.x * GTM;
    int t = threadIdx.x;

    // load B (128x128) to smem
    if (!transB) {
        for (int i = t; i < 4096; i += 256) {           // float4 units
            int k = i >> 5, j4 = i & 31;
            *(float4*)&Bs[k * BS_STRIDE + j4 * 4] =
                *(const float4*)&B[k * 128 + j4 * 4];
        }
    } else {
        for (int i = t; i < 16384; i += 256) {          // scalar transpose
            int k = i >> 7, j = i & 127;
            Bs[k * BS_STRIDE + j] = B[j * 128 + k];
        }
    }
    // load A tile (64x128) to smem
    for (int i = t; i < 2048; i += 256) {
        int r = i >> 5, j4 = i & 31;
        int row = row0 + r;
        float4 v = make_float4(0.f, 0.f, 0.f, 0.f);
        if (row < rows) v = *(const float4*)&A[(long)row * 128 + j4 * 4];
        *(float4*)&As[r * AS_STRIDE + j4 * 4] = v;
    }
    __syncthreads();

    int ty = t >> 4, tx = t & 15;
    int r0 = ty * 4, c0 = tx * 8;
    float acc[4][8];
#pragma unroll
    for (int i = 0; i < 4; i++)
#pragma unroll
        for (int j = 0; j < 8; j++) acc[i][j] = 0.f;

    const float* Asr = As + r0 * AS_STRIDE;
#pragma unroll 8
    for (int k = 0; k < 128; k++) {
        float a0 = Asr[k];
        float a1 = Asr[AS_STRIDE + k];
        float a2 = Asr[2 * AS_STRIDE + k];
        float a3 = Asr[3 * AS_STRIDE + k];
        float4 b0 = *(float4*)&Bs[k * BS_STRIDE + c0];
        float4 b1 = *(float4*)&Bs[k * BS_STRIDE + c0 + 4];
        float bv[8] = {b0.x, b0.y, b0.z, b0.w, b1.x, b1.y, b1.z, b1.w};
#pragma unroll
        for (int j = 0; j < 8; j++) {
            acc[0][j] = fmaf(a0, bv[j], acc[0][j]);
            acc[1][j] = fmaf(a1, bv[j], acc[1][j]);
            acc[2][j] = fmaf(a2, bv[j], acc[2][j]);
            acc[3][j] = fmaf(a3, bv[j], acc[3][j]);
        }
    }

#pragma unroll
    for (int i = 0; i < 4; i++) {
        int row = row0 + r0 + i;
        if (row < rows) {
            float s = rowscale ? rowscale[row] : 1.0f;
            float4 v0 = make_float4(acc[i][0] * s, acc[i][1] * s,
                                    acc[i][2] * s, acc[i][3] * s);
            float4 v1 = make_float4(acc[i][4] * s, acc[i][5] * s,
                                    acc[i][6] * s, acc[i][7] * s);
            *(float4*)&C[(long)row * 128 + c0] = v0;
            *(float4*)&C[(long)row * 128 + c0 + 4] = v1;
        }
    }
}

// ---------------- aggregation: out[d] = dinv[d]*(sum h'[src] + h'[d]) + b ----
__global__ void agg_kernel(const float* __restrict__ h,
                           const int* __restrict__ rowptr,
                           const int* __restrict__ col,
                           const float* __restrict__ dinv,
                           const float* __restrict__ bias,
                           float* __restrict__ out, int n) {
    int warp = (blockIdx.x * blockDim.x + threadIdx.x) >> 5;
    int lane = threadIdx.x & 31;
    if (warp >= n) return;

    int beg = rowptr[warp];
    int end = rowptr[warp + 1];

    float4 acc = *(const float4*)&h[(long)warp * 128 + lane * 4]; // self loop

    int e = beg;
    for (; e + 4 <= end; e += 4) {
        int s0 = col[e], s1 = col[e + 1], s2 = col[e + 2], s3 = col[e + 3];
        float4 v0 = *(const float4*)&h[(long)s0 * 128 + lane * 4];
        float4 v1 = *(const float4*)&h[(long)s1 * 128 + lane * 4];
        float4 v2 = *(const float4*)&h[(long)s2 * 128 + lane * 4];
        float4 v3 = *(const float4*)&h[(long)s3 * 128 + lane * 4];
        acc.x += v0.x + v1.x + v2.x + v3.x;
        acc.y += v0.y + v1.y + v2.y + v3.y;
        acc.z += v0.z + v1.z + v2.z + v3.z;
        acc.w += v0.w + v1.w + v2.w + v3.w;
    }
    for (; e < end; e++) {
        int s = col[e];
        float4 v = *(const float4*)&h[(long)s * 128 + lane * 4];
        acc.x += v.x; acc.y += v.y; acc.z += v.z; acc.w += v.w;
    }

    float dv = dinv[warp];
    float4 bb = *(const float4*)&bias[lane * 4];
    float4 o = make_float4(acc.x * dv + bb.x, acc.y * dv + bb.y,
                           acc.z * dv + bb.z, acc.w * dv + bb.w);
    *(float4*)&out[(long)warp * 128 + lane * 4] = o;
}

// ---------------- gather head/tail embeddings --------------------------------
__global__ void gather_kernel(const float* __restrict__ x,
                              const int* __restrict__ head,
                              const int* __restrict__ tail,
                              float* __restrict__ Hg, float* __restrict__ Tg) {
    int b = blockIdx.x;
    int t = threadIdx.x; // 128
    Hg[(long)b * 128 + t] = x[(long)head[b] * 128 + t];
    Tg[(long)b * 128 + t] = x[(long)tail[b] * 128 + t];
}

// ---------------- fused scorer: out[b,r] = head_b . (S_r . tail_b) -----------
// block: 64 batch rows x relation r. P = H_tile @ S_r in registers, then
// rowwise dot with tail, warp shfl reduction across the 16 col-owners.
#define SB 64
__global__ void score_kernel(const float* __restrict__ Hg,
                             const float* __restrict__ Tg,
                             const float* __restrict__ S,
                             float* __restrict__ out) {
    extern __shared__ float sm[];
    float* Ss = sm;                    // 128 x 132
    float* Hs = sm + 128 * BS_STRIDE;  // 64 x 132

    int r = blockIdx.y;
    const float* Srel = S + (long)r * 16384;
    int b0 = blockIdx.x * SB;
    int t = threadIdx.x;

    for (int i = t; i < 4096; i += 256) {
        int k = i >> 5, j4 = i & 31;
        *(float4*)&Ss[k * BS_STRIDE + j4 * 4] =
            *(const float4*)&Srel[k * 128 + j4 * 4];
    }
    for (int i = t; i < 2048; i += 256) {
        int rr = i >> 5, j4 = i & 31;
        *(float4*)&Hs[rr * AS_STRIDE + j4 * 4] =
            *(const float4*)&Hg[(long)(b0 + rr) * 128 + j4 * 4];
    }
    __syncthreads();

    int ty = t >> 4, tx = t & 15;
    int r0 = ty * 4, c0 = tx * 8;
    float acc[4][8];
#pragma unroll
    for (int i = 0; i < 4; i++)
#pragma unroll
        for (int j = 0; j < 8; j++) acc[i][j] = 0.f;

    const float* Hsr = Hs + r0 * AS_STRIDE;
#pragma unroll 8
    for (int k = 0; k < 128; k++) {
        float a0 = Hsr[k];
        float a1 = Hsr[AS_STRIDE + k];
        float a2 = Hsr[2 * AS_STRIDE + k];
        float a3 = Hsr[3 * AS_STRIDE + k];
        float4 s0 = *(float4*)&Ss[k * BS_STRIDE + c0];
        float4 s1 = *(float4*)&Ss[k * BS_STRIDE + c0 + 4];
        float sv[8] = {s0.x, s0.y, s0.z, s0.w, s1.x, s1.y, s1.z, s1.w};
#pragma unroll
        for (int j = 0; j < 8; j++) {
            acc[0][j] = fmaf(a0, sv[j], acc[0][j]);
            acc[1][j] = fmaf(a1, sv[j], acc[1][j]);
            acc[2][j] = fmaf(a2, sv[j], acc[2][j]);
            acc[3][j] = fmaf(a3, sv[j], acc[3][j]);
        }
    }

    float p[4];
#pragma unroll
    for (int i = 0; i < 4; i++) {
        int row = b0 + r0 + i;
        float4 t0 = *(const float4*)&Tg[(long)row * 128 + c0];
        float4 t1 = *(const float4*)&Tg[(long)row * 128 + c0 + 4];
        p[i] = acc[i][0] * t0.x + acc[i][1] * t0.y + acc[i][2] * t0.z +
               acc[i][3] * t0.w + acc[i][4] * t1.x + acc[i][5] * t1.y +
               acc[i][6] * t1.z + acc[i][7] * t1.w;
    }
    // reduce across the 16 column-owner lanes (xor widths stay within the half)
#pragma unroll
    for (int off = 8; off > 0; off >>= 1) {
#pragma unroll
        for (int i = 0; i < 4; i++)
            p[i] += __shfl_xor_sync(0xffffffffu, p[i], off);
    }
    if (tx == 0) {
#pragma unroll
        for (int i = 0; i < 4; i++)
            out[(long)(b0 + r0 + i) * NREL + r] = p[i];
    }
}

// ---------------- launch -----------------------------------------------------
extern "C" void kernel_launch(void* const* d_in, const int* in_sizes, int n_in,
                              void* d_out, int out_size) {
    const float* init_emb = (const float*)d_in[0];
    const float* W1       = (const float*)d_in[1];
    const float* b1       = (const float*)d_in[2];
    const float* W2       = (const float*)d_in[3];
    const float* b2       = (const float*)d_in[4];
    const float* Rp       = (const float*)d_in[5];
    const float* Mp       = (const float*)d_in[6];
    const int*   head     = (const int*)d_in[7];
    const int*   tail     = (const int*)d_in[8];
    const int*   ei       = (const int*)d_in[9];
    float* out = (float*)d_out;

    const int* src = ei;
    const int* dst = ei + NEDGES;

    float *p_h, *p_x1, *p_x2, *p_dinv, *p_T, *p_S, *p_head, *p_tail;
    int *p_cnt, *p_rowptr, *p_cur, *p_col;
    cudaGetSymbolAddress((void**)&p_h, g_h);
    cudaGetSymbolAddress((void**)&p_x1, g_x1);
    cudaGetSymbolAddress((void**)&p_x2, g_x2);
    cudaGetSymbolAddress((void**)&p_dinv, g_dinv);
    cudaGetSymbolAddress((void**)&p_cnt, g_cnt);
    cudaGetSymbolAddress((void**)&p_rowptr, g_rowptr);
    cudaGetSymbolAddress((void**)&p_cur, g_cur);
    cudaGetSymbolAddress((void**)&p_col, g_col);
    cudaGetSymbolAddress((void**)&p_T, g_T);
    cudaGetSymbolAddress((void**)&p_S, g_S);
    cudaGetSymbolAddress((void**)&p_head, g_head);
    cudaGetSymbolAddress((void**)&p_tail, g_tail);

    const int SMEM = (128 * BS_STRIDE + 64 * AS_STRIDE) * (int)sizeof(float);
    cudaFuncSetAttribute(gemm128_kernel,
                         cudaFuncAttributeMaxDynamicSharedMemorySize, SMEM);
    cudaFuncSetAttribute(score_kernel,
                         cudaFuncAttributeMaxDynamicSharedMemorySize, SMEM);

    // CSR build (graph structure shared by both layers)
    zero_cnt_kernel<<<(NNODES + 255) / 256, 256>>>(p_cnt, NNODES);
    count_kernel<<<NEDGES / 256, 256>>>(dst, p_cnt, NEDGES);
    scan_kernel<<<1, 1024>>>(p_cnt, p_rowptr, p_cur, p_dinv, NNODES);
    fill_kernel<<<NEDGES / 256, 256>>>(src, dst, p_cur, p_col, NEDGES);

    dim3 ggrid((NNODES + GTM - 1) / GTM, 1);
    int agg_blocks = (NNODES * 32 + 255) / 256;

    // layer 1
    gemm128_kernel<<<ggrid, 256, SMEM>>>(init_emb, 0, W1, 0, p_h, 0,
                                         NNODES, 0, p_dinv);
    agg_kernel<<<agg_blocks, 256>>>(p_h, p_rowptr, p_col, p_dinv, b1, p_x1, NNODES);
    // layer 2
    gemm128_kernel<<<ggrid, 256, SMEM>>>(p_x1, 0, W2, 0, p_h, 0,
                                         NNODES, 0, p_dinv);
    agg_kernel<<<agg_blocks, 256>>>(p_h, p_rowptr, p_col, p_dinv, b2, p_x2, NNODES);

    // gather batch embeddings
    gather_kernel<<<NBATCH, 128>>>(p_x2, head, tail, p_head, p_tail);

    // S_r = (R_r @ M) @ R_r^T
    dim3 rgrid(2, NREL);
    gemm128_kernel<<<rgrid, 256, SMEM>>>(Rp, 16384, Mp, 0, p_T, 16384,
                                         128, 0, nullptr);
    gemm128_kernel<<<rgrid, 256, SMEM>>>(p_T, 16384, Rp, 16384, p_S, 16384,
                                         128, 1, nullptr);

    // fused score: out[b, r]
    dim3 sgrid(NBATCH / SB, NREL);
    score_kernel<<<sgrid, 256, SMEM>>>(p_head, p_tail, p_S, out);
}

// round 3
// speedup vs baseline: 1.5679x; 1.5679x over previous
#include <cuda_runtime.h>
#include <cuda_bf16.h>
#include <cstdint>
#include <math.h>

#define NNODES 50000
#define NEDGES 800000
#define DIM    128
#define NREL   86
#define NBATCH 2048
#define LDT    136   // bf16 smem stride (elems)
#define LDH    132   // fp32 head smem stride (elems)

// ---------------- scratch (device globals; no allocation allowed) ------------
__device__ float g_h  [NNODES * DIM];
__device__ float g_x1 [NNODES * DIM];
__device__ float g_x2 [NNODES * DIM];
__device__ float g_dinv[NNODES];
__device__ int   g_cnt [NNODES];
__device__ int   g_rowptr[NNODES + 1];
__device__ int   g_cur [NNODES];
__device__ int   g_col [NEDGES];
__device__ float g_T   [NREL * DIM * DIM];
__device__ __nv_bfloat16 g_WThi[3 * DIM * DIM];
__device__ __nv_bfloat16 g_WTlo[3 * DIM * DIM];
__device__ __nv_bfloat16 g_Rhi [NREL * DIM * DIM];
__device__ __nv_bfloat16 g_Rlo [NREL * DIM * DIM];
__device__ __nv_bfloat16 g_Shi [NREL * DIM * DIM];
__device__ __nv_bfloat16 g_Slo [NREL * DIM * DIM];
__device__ float g_head[NBATCH * DIM];
__device__ __nv_bfloat16 g_thi[NBATCH * DIM];
__device__ __nv_bfloat16 g_tlo[NBATCH * DIM];

// ==================== helpers ===============================================
__device__ __forceinline__ uint32_t smem_u32(const void* p) {
    uint32_t a;
    asm("{ .reg .u64 t; cvta.to.shared.u64 t, %1; cvt.u32.u64 %0, t; }"
        : "=r"(a) : "l"(p));
    return a;
}

__device__ __forceinline__ void ldm_x4(uint32_t* r, uint32_t addr) {
    asm volatile("ldmatrix.sync.aligned.m8n8.x4.shared.b16 {%0,%1,%2,%3}, [%4];"
                 : "=r"(r[0]), "=r"(r[1]), "=r"(r[2]), "=r"(r[3]) : "r"(addr));
}

__device__ __forceinline__ void mma16816(float* d, const uint32_t* a,
                                         const uint32_t* b) {
    asm volatile(
        "mma.sync.aligned.m16n8k16.row.col.f32.bf16.bf16.f32 "
        "{%0,%1,%2,%3}, {%4,%5,%6,%7}, {%8,%9}, {%0,%1,%2,%3};"
        : "+f"(d[0]), "+f"(d[1]), "+f"(d[2]), "+f"(d[3])
        : "r"(a[0]), "r"(a[1]), "r"(a[2]), "r"(a[3]), "r"(b[0]), "r"(b[1]));
}

// split two fp32 -> packed bf16x2 hi + lo
__device__ __forceinline__ void cvt2(float a, float b, uint32_t& hi, uint32_t& lo) {
    __nv_bfloat162 h = __floats2bfloat162_rn(a, b);
    float ra = a - __bfloat162float(h.x);
    float rb = b - __bfloat162float(h.y);
    __nv_bfloat162 l = __floats2bfloat162_rn(ra, rb);
    hi = *(uint32_t*)&h;
    lo = *(uint32_t*)&l;
}
__device__ __forceinline__ void cvt8(const float* v, uint4& hi, uint4& lo) {
    uint32_t h[4], l[4];
#pragma unroll
    for (int i = 0; i < 4; i++) cvt2(v[2 * i], v[2 * i + 1], h[i], l[i]);
    hi = make_uint4(h[0], h[1], h[2], h[3]);
    lo = make_uint4(l[0], l[1], l[2], l[3]);
}

// ==================== CSR build =============================================
__global__ void zero_cnt_kernel(int* cnt, int n) {
    int i = blockIdx.x * blockDim.x + threadIdx.x;
    if (i < n) cnt[i] = 0;
}
__global__ void count_kernel(const int* __restrict__ dst, int* cnt, int e) {
    int i = blockIdx.x * blockDim.x + threadIdx.x;
    if (i < e) atomicAdd(&cnt[dst[i]], 1);
}
__global__ void scan_kernel(const int* __restrict__ cnt, int* rowptr, int* cur,
                            float* dinv, int n) {
    __shared__ int ssum[1024];
    int t = threadIdx.x;
    int chunk = (n + 1023) / 1024;
    int beg = t * chunk, end = min(beg + chunk, n);
    int s = 0;
    for (int i = beg; i < end; i++) s += cnt[i];
    ssum[t] = s;
    __syncthreads();
    for (int off = 1; off < 1024; off <<= 1) {
        int v = (t >= off) ? ssum[t - off] : 0;
        __syncthreads();
        ssum[t] += v;
        __syncthreads();
    }
    int base = (t == 0) ? 0 : ssum[t - 1];
    for (int i = beg; i < end; i++) {
        rowptr[i] = base; cur[i] = base;
        dinv[i] = rsqrtf((float)(cnt[i] + 1));
        base += cnt[i];
    }
    if (t == 1023) rowptr[n] = ssum[1023];
}
__global__ void fill_kernel(const int* __restrict__ src, const int* __restrict__ dst,
                            int* cur, int* col, int e) {
    int i = blockIdx.x * blockDim.x + threadIdx.x;
    if (i < e) {
        int d = dst[i];
        int p = atomicAdd(&cur[d], 1);
        col[p] = src[i];
    }
}

// ==================== operand prep ==========================================
// transpose + bf16-split W1, W2, M into [n][k] layout
__global__ void prepW_kernel(const float* __restrict__ W1,
                             const float* __restrict__ W2,
                             const float* __restrict__ M,
                             __nv_bfloat16* outHi, __nv_bfloat16* outLo) {
    int mat = blockIdx.x, t = threadIdx.x; // t = output row n
    const float* src = (mat == 0) ? W1 : (mat == 1) ? W2 : M;
    float v[8];
    for (int g = 0; g < 16; g++) {
#pragma unroll
        for (int j = 0; j < 8; j++) v[j] = src[(g * 8 + j) * 128 + t];
        uint4 hi, lo; cvt8(v, hi, lo);
        long off = (long)mat * 16384 + t * 128 + g * 8;
        *(uint4*)&outHi[off] = hi;
        *(uint4*)&outLo[off] = lo;
    }
}

// elementwise bf16 split of relation_param (R stays [f][k] layout)
__global__ void prepR_kernel(const float* __restrict__ R,
                             __nv_bfloat16* outHi, __nv_bfloat16* outLo) {
    long i = (long)(blockIdx.x * blockDim.x + threadIdx.x) * 8;
    if (i >= (long)NREL * 16384) return;
    float v[8];
    float4 a0 = *(const float4*)&R[i];
    float4 a1 = *(const float4*)&R[i + 4];
    v[0]=a0.x; v[1]=a0.y; v[2]=a0.z; v[3]=a0.w;
    v[4]=a1.x; v[5]=a1.y; v[6]=a1.z; v[7]=a1.w;
    uint4 hi, lo; cvt8(v, hi, lo);
    *(uint4*)&outHi[i] = hi;
    *(uint4*)&outLo[i] = lo;
}

// ==================== HMMA GEMM =============================================
// C[rows,128] = A[rows,128] @ Bmath, where smem B holds Bs[n][k] (bf16 hi/lo,
// i.e. Bmath[k][n] = Bs[n][k]).  A is fp32, converted to bf16 hi/lo in-block.
// Output: fp32 C (optional rowscale)  OR  bf16-split row-major (SoHi/SoLo).
__global__ void __launch_bounds__(256)
gemm_mma(const float* __restrict__ A, long strideA,
         const __nv_bfloat16* __restrict__ Bhi,
         const __nv_bfloat16* __restrict__ Blo, long strideB,
         float* __restrict__ C, long strideC,
         const float* __restrict__ rowscale,
         __nv_bfloat16* SoHi, __nv_bfloat16* SoLo, long strideS,
         int rows) {
    extern __shared__ char smem[];
    __nv_bfloat16* sAh = (__nv_bfloat16*)smem;
    __nv_bfloat16* sAl = sAh + 128 * LDT;
    __nv_bfloat16* sBh = sAl + 128 * LDT;
    __nv_bfloat16* sBl = sBh + 128 * LDT;

    int t = threadIdx.x, wid = t >> 5, l = t & 31;
    int batch = blockIdx.y;
    const float* Ab = A + (long)batch * strideA;
    const __nv_bfloat16* Bhb = Bhi + (long)batch * strideB;
    const __nv_bfloat16* Blb = Blo + (long)batch * strideB;
    int row0 = blockIdx.x * 128;

    // ---- stage A (fp32 -> bf16 split) and B (bf16 copy) into padded smem ----
    {
        int rr = t >> 1, hc = (t & 1) * 64;
        int grow = row0 + rr;
        const float* ar = Ab + (long)grow * 128 + hc;
        float v[8];
#pragma unroll
        for (int g = 0; g < 8; g++) {
            if (grow < rows) {
                float4 a0 = *(const float4*)&ar[g * 8];
                float4 a1 = *(const float4*)&ar[g * 8 + 4];
                v[0]=a0.x; v[1]=a0.y; v[2]=a0.z; v[3]=a0.w;
                v[4]=a1.x; v[5]=a1.y; v[6]=a1.z; v[7]=a1.w;
            } else {
#pragma unroll
                for (int j = 0; j < 8; j++) v[j] = 0.f;
            }
            uint4 hi, lo; cvt8(v, hi, lo);
            int so = rr * LDT + hc + g * 8;
            *(uint4*)&sAh[so] = hi;
            *(uint4*)&sAl[so] = lo;
        }
#pragma unroll
        for (int g = 0; g < 8; g++) {
            long goff = (long)rr * 128 + hc + g * 8;
            int so = rr * LDT + hc + g * 8;
            *(uint4*)&sBh[so] = *(const uint4*)&Bhb[goff];
            *(uint4*)&sBl[so] = *(const uint4*)&Blb[goff];
        }
    }
    __syncthreads();

    uint32_t sAh_u = smem_u32(sAh), sAl_u = smem_u32(sAl);
    uint32_t sBh_u = smem_u32(sBh), sBl_u = smem_u32(sBl);

    int wm = wid >> 2, wn = wid & 3;
    int m0 = wm * 64, n0 = wn * 32;
    int arow = l & 15, acol8 = (l >> 4) * 8;
    int brow = (l & 7) + (l >> 4) * 8, bcol = ((l >> 3) & 1) * 8;

    float acc[4][4][4];
#pragma unroll
    for (int mf = 0; mf < 4; mf++)
#pragma unroll
        for (int nf = 0; nf < 4; nf++)
#pragma unroll
            for (int c = 0; c < 4; c++) acc[mf][nf][c] = 0.f;

#pragma unroll
    for (int ks = 0; ks < 8; ks++) {
        int k0 = ks * 16;
        uint32_t ah[4][4], al[4][4], bh[2][4], bl[2][4];
#pragma unroll
        for (int mf = 0; mf < 4; mf++) {
            uint32_t off = (uint32_t)(((m0 + mf * 16 + arow) * LDT + k0 + acol8) * 2);
            ldm_x4(ah[mf], sAh_u + off);
            ldm_x4(al[mf], sAl_u + off);
        }
#pragma unroll
        for (int nh = 0; nh < 2; nh++) {
            uint32_t off = (uint32_t)(((n0 + nh * 16 + brow) * LDT + k0 + bcol) * 2);
            ldm_x4(bh[nh], sBh_u + off);
            ldm_x4(bl[nh], sBl_u + off);
        }
#pragma unroll
        for (int mf = 0; mf < 4; mf++)
#pragma unroll
            for (int nf = 0; nf < 4; nf++) {
                const uint32_t* bhp = &bh[nf >> 1][(nf & 1) * 2];
                const uint32_t* blp = &bl[nf >> 1][(nf & 1) * 2];
                mma16816(acc[mf][nf], ah[mf], bhp);
                mma16816(acc[mf][nf], ah[mf], blp);
                mma16816(acc[mf][nf], al[mf], bhp);
            }
    }

    // ---- epilogue ----
    int r01 = l >> 2, cql = (l & 3) * 2;
    if (SoHi) {
        __nv_bfloat16* oh = SoHi + (long)batch * strideS;
        __nv_bfloat16* ol = SoLo + (long)batch * strideS;
#pragma unroll
        for (int mf = 0; mf < 4; mf++) {
            int ra = m0 + mf * 16 + r01, rb = ra + 8;
#pragma unroll
            for (int nf = 0; nf < 4; nf++) {
                int col = n0 + nf * 8 + cql;
                uint32_t hi, lo;
                cvt2(acc[mf][nf][0], acc[mf][nf][1], hi, lo);
                *(uint32_t*)&oh[ra * 128 + col] = hi;
                *(uint32_t*)&ol[ra * 128 + col] = lo;
                cvt2(acc[mf][nf][2], acc[mf][nf][3], hi, lo);
                *(uint32_t*)&oh[rb * 128 + col] = hi;
                *(uint32_t*)&ol[rb * 128 + col] = lo;
            }
        }
    } else {
        float* Cb = C + (long)batch * strideC;
#pragma unroll
        for (int mf = 0; mf < 4; mf++) {
            int ga = row0 + m0 + mf * 16 + r01, gb = ga + 8;
            float sa = 1.f, sbf = 1.f;
            if (rowscale) {
                if (ga < rows) sa = rowscale[ga];
                if (gb < rows) sbf = rowscale[gb];
            }
#pragma unroll
            for (int nf = 0; nf < 4; nf++) {
                int col = n0 + nf * 8 + cql;
                if (ga < rows) {
                    float2 v = make_float2(acc[mf][nf][0] * sa, acc[mf][nf][1] * sa);
                    *(float2*)&Cb[(long)ga * 128 + col] = v;
                }
                if (gb < rows) {
                    float2 v = make_float2(acc[mf][nf][2] * sbf, acc[mf][nf][3] * sbf);
                    *(float2*)&Cb[(long)gb * 128 + col] = v;
                }
            }
        }
    }
}

// ==================== aggregation ===========================================
__global__ void agg_kernel(const float* __restrict__ h,
                           const int* __restrict__ rowptr,
                           const int* __restrict__ col,
                           const float* __restrict__ dinv,
                           const float* __restrict__ bias,
                           float* __restrict__ out, int n) {
    int warp = (blockIdx.x * blockDim.x + threadIdx.x) >> 5;
    int lane = threadIdx.x & 31;
    if (warp >= n) return;
    int beg = rowptr[warp], end = rowptr[warp + 1];
    float4 acc = *(const float4*)&h[(long)warp * 128 + lane * 4];
    int e = beg;
    for (; e + 4 <= end; e += 4) {
        int s0 = col[e], s1 = col[e + 1], s2 = col[e + 2], s3 = col[e + 3];
        float4 v0 = *(const float4*)&h[(long)s0 * 128 + lane * 4];
        float4 v1 = *(const float4*)&h[(long)s1 * 128 + lane * 4];
        float4 v2 = *(const float4*)&h[(long)s2 * 128 + lane * 4];
        float4 v3 = *(const float4*)&h[(long)s3 * 128 + lane * 4];
        acc.x += v0.x + v1.x + v2.x + v3.x;
        acc.y += v0.y + v1.y + v2.y + v3.y;
        acc.z += v0.z + v1.z + v2.z + v3.z;
        acc.w += v0.w + v1.w + v2.w + v3.w;
    }
    for (; e < end; e++) {
        int s = col[e];
        float4 v = *(const float4*)&h[(long)s * 128 + lane * 4];
        acc.x += v.x; acc.y += v.y; acc.z += v.z; acc.w += v.w;
    }
    float dv = dinv[warp];
    float4 bb = *(const float4*)&bias[lane * 4];
    *(float4*)&out[(long)warp * 128 + lane * 4] =
        make_float4(acc.x * dv + bb.x, acc.y * dv + bb.y,
                    acc.z * dv + bb.z, acc.w * dv + bb.w);
}

// ==================== gather batch embeddings ===============================
__global__ void gather_kernel(const float* __restrict__ x,
                              const int* __restrict__ head,
                              const int* __restrict__ tail,
                              float* __restrict__ Hg,
                              __nv_bfloat16* Thi, __nv_bfloat16* Tlo) {
    int b = blockIdx.x * 128 + threadIdx.x;
    const float4* hr = (const float4*)(x + (long)head[b] * 128);
    float4* ho = (float4*)(Hg + (long)b * 128);
#pragma unroll 8
    for (int j = 0; j < 32; j++) ho[j] = hr[j];

    const float* tr = x + (long)tail[b] * 128;
    float v[8];
#pragma unroll
    for (int g = 0; g < 16; g++) {
        float4 a0 = *(const float4*)&tr[g * 8];
        float4 a1 = *(const float4*)&tr[g * 8 + 4];
        v[0]=a0.x; v[1]=a0.y; v[2]=a0.z; v[3]=a0.w;
        v[4]=a1.x; v[5]=a1.y; v[6]=a1.z; v[7]=a1.w;
        uint4 hi, lo; cvt8(v, hi, lo);
        long off = (long)b * 128 + g * 8;
        *(uint4*)&Thi[off] = hi;
        *(uint4*)&Tlo[off] = lo;
    }
}

// ==================== scorer ================================================
// block = (batch tile of 128) x (pair of relations).
// P2[b,e] = sum_f tail[b,f] * S_r[e,f]  (HMMA split)
// out[b,r] = sum_e P2[b,e] * head[b,e]  (fp32, fragment-local)
__global__ void __launch_bounds__(256)
score_mma(const __nv_bfloat16* __restrict__ Thi,
          const __nv_bfloat16* __restrict__ Tlo,
          const __nv_bfloat16* __restrict__ Shi,
          const __nv_bfloat16* __restrict__ Slo,
          const float* __restrict__ Hg, float* __restrict__ out) {
    extern __shared__ char smem[];
    __nv_bfloat16* sAh = (__nv_bfloat16*)smem;
    __nv_bfloat16* sAl = sAh + 128 * LDT;
    __nv_bfloat16* sBh = sAl + 128 * LDT;
    __nv_bfloat16* sBl = sBh + 128 * LDT;
    float* Hs = (float*)(sBl + 128 * LDT);       // [128][LDH]
    float* out_s = Hs + 128 * LDH;               // [128]

    int t = threadIdx.x, wid = t >> 5, l = t & 31;
    int tile = blockIdx.x, rpair = blockIdx.y;
    int rr = t >> 1, hc = (t & 1) * 64;

    // stage tail tile + head tile
    {
        long base = (long)(tile * 128 + rr) * 128 + hc;
#pragma unroll
        for (int g = 0; g < 8; g++) {
            int so = rr * LDT + hc + g * 8;
            *(uint4*)&sAh[so] = *(const uint4*)&Thi[base + g * 8];
            *(uint4*)&sAl[so] = *(const uint4*)&Tlo[base + g * 8];
        }
        const float* hr = Hg + (long)(tile * 128 + rr) * 128 + hc;
#pragma unroll
        for (int g = 0; g < 8; g++) {
            float4 v0 = *(const float4*)&hr[g * 8];
            float4 v1 = *(const float4*)&hr[g * 8 + 4];
            int so = rr * LDH + hc + g * 8;
            *(float4*)&Hs[so] = v0;
            *(float4*)&Hs[so + 4] = v1;
        }
    }

    uint32_t sAh_u = smem_u32(sAh), sAl_u = smem_u32(sAl);
    uint32_t sBh_u = smem_u32(sBh), sBl_u = smem_u32(sBl);

    int wm = wid >> 2, wn = wid & 3;
    int m0 = wm * 64, n0 = wn * 32;
    int arow = l & 15, acol8 = (l >> 4) * 8;
    int brow = (l & 7) + (l >> 4) * 8, bcol = ((l >> 3) & 1) * 8;
    int r01 = l >> 2, cql = (l & 3) * 2;

    for (int i = 0; i < 2; i++) {
        int r = rpair * 2 + i;
        __syncthreads();   // protect B smem + out_s from prior readers
        // stage S_r
        {
            long base = (long)r * 16384 + rr * 128 + hc;
#pragma unroll
            for (int g = 0; g < 8; g++) {
                int so = rr * LDT + hc + g * 8;
                *(uint4*)&sBh[so] = *(const uint4*)&Shi[base + g * 8];
                *(uint4*)&sBl[so] = *(const uint4*)&Slo[base + g * 8];
            }
        }
        if (t < 128) out_s[t] = 0.f;
        __syncthreads();

        float acc[4][4][4];
#pragma unroll
        for (int mf = 0; mf < 4; mf++)
#pragma unroll
            for (int nf = 0; nf < 4; nf++)
#pragma unroll
                for (int c = 0; c < 4; c++) acc[mf][nf][c] = 0.f;

#pragma unroll
        for (int ks = 0; ks < 8; ks++) {
            int k0 = ks * 16;
            uint32_t ah[4][4], al[4][4], bh[2][4], bl[2][4];
#pragma unroll
            for (int mf = 0; mf < 4; mf++) {
                uint32_t off = (uint32_t)(((m0 + mf * 16 + arow) * LDT + k0 + acol8) * 2);
                ldm_x4(ah[mf], sAh_u + off);
                ldm_x4(al[mf], sAl_u + off);
            }
#pragma unroll
            for (int nh = 0; nh < 2; nh++) {
                uint32_t off = (uint32_t)(((n0 + nh * 16 + brow) * LDT + k0 + bcol) * 2);
                ldm_x4(bh[nh], sBh_u + off);
                ldm_x4(bl[nh], sBl_u + off);
            }
#pragma unroll
            for (int mf = 0; mf < 4; mf++)
#pragma unroll
                for (int nf = 0; nf < 4; nf++) {
                    const uint32_t* bhp = &bh[nf >> 1][(nf & 1) * 2];
                    const uint32_t* blp = &bl[nf >> 1][(nf & 1) * 2];
                    mma16816(acc[mf][nf], ah[mf], bhp);
                    mma16816(acc[mf][nf], ah[mf], blp);
                    mma16816(acc[mf][nf], al[mf], bhp);
                }
        }

        // fragment-local dot with head
        float part[4][2];
#pragma unroll
        for (int mf = 0; mf < 4; mf++) { part[mf][0] = 0.f; part[mf][1] = 0.f; }
#pragma unroll
        for (int mf = 0; mf < 4; mf++) {
            int ra = m0 + mf * 16 + r01;
#pragma unroll
            for (int nf = 0; nf < 4; nf++) {
                int col = n0 + nf * 8 + cql;
                float2 h0 = *(float2*)&Hs[ra * LDH + col];
                float2 h1 = *(float2*)&Hs[(ra + 8) * LDH + col];
                part[mf][0] += acc[mf][nf][0] * h0.x + acc[mf][nf][1] * h0.y;
                part[mf][1] += acc[mf][nf][2] * h1.x + acc[mf][nf][3] * h1.y;
            }
        }
#pragma unroll
        for (int mf = 0; mf < 4; mf++) {
#pragma unroll
            for (int hh = 0; hh < 2; hh++) {
                part[mf][hh] += __shfl_xor_sync(0xffffffffu, part[mf][hh], 1);
                part[mf][hh] += __shfl_xor_sync(0xffffffffu, part[mf][hh], 2);
            }
        }
        if ((l & 3) == 0) {
#pragma unroll
            for (int mf = 0; mf < 4; mf++) {
                atomicAdd(&out_s[m0 + mf * 16 + r01], part[mf][0]);
                atomicAdd(&out_s[m0 + mf * 16 + r01 + 8], part[mf][1]);
            }
        }
        __syncthreads();
        if (t < 128)
            out[(long)(tile * 128 + t) * NREL + r] = out_s[t];
    }
}

// ==================== launch ================================================
extern "C" void kernel_launch(void* const* d_in, const int* in_sizes, int n_in,
                              void* d_out, int out_size) {
    const float* init_emb = (const float*)d_in[0];
    const float* W1       = (const float*)d_in[1];
    const float* b1       = (const float*)d_in[2];
    const float* W2       = (const float*)d_in[3];
    const float* b2       = (const float*)d_in[4];
    const float* Rp       = (const float*)d_in[5];
    const float* Mp       = (const float*)d_in[6];
    const int*   head     = (const int*)d_in[7];
    const int*   tail     = (const int*)d_in[8];
    const int*   ei       = (const int*)d_in[9];
    float* out = (float*)d_out;

    const int* src = ei;
    const int* dst = ei + NEDGES;

    float *p_h, *p_x1, *p_x2, *p_dinv, *p_T, *p_head;
    __nv_bfloat16 *p_WThi, *p_WTlo, *p_Rhi, *p_Rlo, *p_Shi, *p_Slo, *p_thi, *p_tlo;
    int *p_cnt, *p_rowptr, *p_cur, *p_col;
    cudaGetSymbolAddress((void**)&p_h, g_h);
    cudaGetSymbolAddress((void**)&p_x1, g_x1);
    cudaGetSymbolAddress((void**)&p_x2, g_x2);
    cudaGetSymbolAddress((void**)&p_dinv, g_dinv);
    cudaGetSymbolAddress((void**)&p_cnt, g_cnt);
    cudaGetSymbolAddress((void**)&p_rowptr, g_rowptr);
    cudaGetSymbolAddress((void**)&p_cur, g_cur);
    cudaGetSymbolAddress((void**)&p_col, g_col);
    cudaGetSymbolAddress((void**)&p_T, g_T);
    cudaGetSymbolAddress((void**)&p_WThi, g_WThi);
    cudaGetSymbolAddress((void**)&p_WTlo, g_WTlo);
    cudaGetSymbolAddress((void**)&p_Rhi, g_Rhi);
    cudaGetSymbolAddress((void**)&p_Rlo, g_Rlo);
    cudaGetSymbolAddress((void**)&p_Shi, g_Shi);
    cudaGetSymbolAddress((void**)&p_Slo, g_Slo);
    cudaGetSymbolAddress((void**)&p_head, g_head);
    cudaGetSymbolAddress((void**)&p_thi, g_thi);
    cudaGetSymbolAddress((void**)&p_tlo, g_tlo);

    const int GEMM_SMEM  = 4 * 128 * LDT * 2;                       // 139264
    const int SCORE_SMEM = GEMM_SMEM + 128 * LDH * 4 + 128 * 4;     // 207360
    cudaFuncSetAttribute(gemm_mma,  cudaFuncAttributeMaxDynamicSharedMemorySize, GEMM_SMEM);
    cudaFuncSetAttribute(score_mma, cudaFuncAttributeMaxDynamicSharedMemorySize, SCORE_SMEM);

    // CSR build
    zero_cnt_kernel<<<(NNODES + 255) / 256, 256>>>(p_cnt, NNODES);
    count_kernel<<<NEDGES / 256, 256>>>(dst, p_cnt, NEDGES);
    scan_kernel<<<1, 1024>>>(p_cnt, p_rowptr, p_cur, p_dinv, NNODES);
    fill_kernel<<<NEDGES / 256, 256>>>(src, dst, p_cur, p_col, NEDGES);

    // operand prep
    prepW_kernel<<<3, 128>>>(W1, W2, Mp, p_WThi, p_WTlo);
    prepR_kernel<<<(NREL * 16384 / 8 + 255) / 256, 256>>>(Rp, p_Rhi, p_Rlo);

    int ntiles = (NNODES + 127) / 128;  // 391
    int agg_blocks = (NNODES * 32 + 255) / 256;

    // layer 1: h = (x @ W1) * dinv
    gemm_mma<<<dim3(ntiles, 1), 256, GEMM_SMEM>>>(
        init_emb, 0, p_WThi, p_WTlo, 0, p_h, 0, p_dinv,
        nullptr, nullptr, 0, NNODES);
    agg_kernel<<<agg_blocks, 256>>>(p_h, p_rowptr, p_col, p_dinv, b1, p_x1, NNODES);
    // layer 2
    gemm_mma<<<dim3(ntiles, 1), 256, GEMM_SMEM>>>(
        p_x1, 0, p_WThi + 16384, p_WTlo + 16384, 0, p_h, 0, p_dinv,
        nullptr, nullptr, 0, NNODES);
    agg_kernel<<<agg_blocks, 256>>>(p_h, p_rowptr, p_col, p_dinv, b2, p_x2, NNODES);

    // gather batch embeddings
    gather_kernel<<<NBATCH / 128, 128>>>(p_x2, head, tail, p_head, p_thi, p_tlo);

    // T_r = R_r @ M    (B = M^T prepped, shared across relations)
    gemm_mma<<<dim3(1, NREL), 256, GEMM_SMEM>>>(
        Rp, 16384, p_WThi + 2 * 16384, p_WTlo + 2 * 16384, 0,
        p_T, 16384, nullptr, nullptr, nullptr, 0, 128);
    // S_r = T_r @ R_r^T  (B = R_r direct) -> bf16 split
    gemm_mma<<<dim3(1, NREL), 256, GEMM_SMEM>>>(
        p_T, 16384, p_Rhi, p_Rlo, 16384,
        nullptr, 0, nullptr, p_Shi, p_Slo, 16384, 128);

    // fused scorer
    score_mma<<<dim3(NBATCH / 128, NREL / 2), 256, SCORE_SMEM>>>(
        p_thi, p_tlo, p_Shi, p_Slo, p_head, out);
}

// round 5
// speedup vs baseline: 1.8387x; 1.1727x over previous
#include <cuda_runtime.h>
#include <cuda_bf16.h>
#include <cstdint>
#include <math.h>

#define NNODES 50000
#define NEDGES 800000
#define DIM    128
#define NREL   86
#define NBATCH 2048
#define LDT    136   // bf16 smem stride (elems)
#define LDH    132   // fp32 head smem stride (elems)

// ---------------- scratch (device globals; no allocation allowed) ------------
__device__ float g_h  [NNODES * DIM];
__device__ float g_x1 [NNODES * DIM];
__device__ float g_x2 [NNODES * DIM];
__device__ float g_dinv[NNODES];
__device__ int   g_cnt [NNODES];
__device__ int   g_rowptr[NNODES + 1];
__device__ int   g_cur [NNODES];
__device__ int   g_col [NEDGES];
__device__ float g_T   [NREL * DIM * DIM];
__device__ __nv_bfloat16 g_WThi[3 * DIM * DIM];
__device__ __nv_bfloat16 g_WTlo[3 * DIM * DIM];
__device__ __nv_bfloat16 g_Rhi [NREL * DIM * DIM];
__device__ __nv_bfloat16 g_Rlo [NREL * DIM * DIM];
__device__ __nv_bfloat16 g_Shi [NREL * DIM * DIM];
__device__ __nv_bfloat16 g_Slo [NREL * DIM * DIM];
__device__ float g_head[NBATCH * DIM];
__device__ __nv_bfloat16 g_thi[NBATCH * DIM];
__device__ __nv_bfloat16 g_tlo[NBATCH * DIM];

// ==================== helpers ===============================================
__device__ __forceinline__ uint32_t smem_u32(const void* p) {
    uint32_t a;
    asm("{ .reg .u64 t; cvta.to.shared.u64 t, %1; cvt.u32.u64 %0, t; }"
        : "=r"(a) : "l"(p));
    return a;
}

__device__ __forceinline__ void ldm_x4(uint32_t* r, uint32_t addr) {
    asm volatile("ldmatrix.sync.aligned.m8n8.x4.shared.b16 {%0,%1,%2,%3}, [%4];"
                 : "=r"(r[0]), "=r"(r[1]), "=r"(r[2]), "=r"(r[3]) : "r"(addr));
}

__device__ __forceinline__ void mma16816(float* d, const uint32_t* a,
                                         const uint32_t* b) {
    asm volatile(
        "mma.sync.aligned.m16n8k16.row.col.f32.bf16.bf16.f32 "
        "{%0,%1,%2,%3}, {%4,%5,%6,%7}, {%8,%9}, {%0,%1,%2,%3};"
        : "+f"(d[0]), "+f"(d[1]), "+f"(d[2]), "+f"(d[3])
        : "r"(a[0]), "r"(a[1]), "r"(a[2]), "r"(a[3]), "r"(b[0]), "r"(b[1]));
}

// split two fp32 -> packed bf16x2 hi + lo
__device__ __forceinline__ void cvt2(float a, float b, uint32_t& hi, uint32_t& lo) {
    __nv_bfloat162 h = __floats2bfloat162_rn(a, b);
    float ra = a - __bfloat162float(h.x);
    float rb = b - __bfloat162float(h.y);
    __nv_bfloat162 l = __floats2bfloat162_rn(ra, rb);
    hi = *(uint32_t*)&h;
    lo = *(uint32_t*)&l;
}
__device__ __forceinline__ void cvt8(const float* v, uint4& hi, uint4& lo) {
    uint32_t h[4], l[4];
#pragma unroll
    for (int i = 0; i < 4; i++) cvt2(v[2 * i], v[2 * i + 1], h[i], l[i]);
    hi = make_uint4(h[0], h[1], h[2], h[3]);
    lo = make_uint4(l[0], l[1], l[2], l[3]);
}

// ==================== CSR build =============================================
__global__ void zero_cnt_kernel(int* cnt, int n) {
    int i = blockIdx.x * blockDim.x + threadIdx.x;
    if (i < n) cnt[i] = 0;
}
__global__ void count_kernel(const int4* __restrict__ dst4, int* cnt, int e4) {
    int i = blockIdx.x * blockDim.x + threadIdx.x;
    if (i < e4) {
        int4 d = dst4[i];
        atomicAdd(&cnt[d.x], 1);
        atomicAdd(&cnt[d.y], 1);
        atomicAdd(&cnt[d.z], 1);
        atomicAdd(&cnt[d.w], 1);
    }
}
__global__ void scan_kernel(const int* __restrict__ cnt, int* rowptr, int* cur,
                            float* dinv, int n) {
    __shared__ int ssum[1024];
    int t = threadIdx.x;
    int chunk = (n + 1023) / 1024;
    int beg = t * chunk, end = min(beg + chunk, n);
    int s = 0;
    for (int i = beg; i < end; i++) s += cnt[i];
    ssum[t] = s;
    __syncthreads();
    for (int off = 1; off < 1024; off <<= 1) {
        int v = (t >= off) ? ssum[t - off] : 0;
        __syncthreads();
        ssum[t] += v;
        __syncthreads();
    }
    int base = (t == 0) ? 0 : ssum[t - 1];
    for (int i = beg; i < end; i++) {
        rowptr[i] = base; cur[i] = base;
        dinv[i] = rsqrtf((float)(cnt[i] + 1));
        base += cnt[i];
    }
    if (t == 1023) rowptr[n] = ssum[1023];
}
__global__ void fill_kernel(const int4* __restrict__ src4,
                            const int4* __restrict__ dst4,
                            int* cur, int* col, int e4) {
    int i = blockIdx.x * blockDim.x + threadIdx.x;
    if (i < e4) {
        int4 d = dst4[i];
        int4 s = src4[i];
        col[atomicAdd(&cur[d.x], 1)] = s.x;
        col[atomicAdd(&cur[d.y], 1)] = s.y;
        col[atomicAdd(&cur[d.z], 1)] = s.z;
        col[atomicAdd(&cur[d.w], 1)] = s.w;
    }
}

// ==================== operand prep ==========================================
// transpose + bf16-split W1, W2, M into [n][k] layout
__global__ void prepW_kernel(const float* __restrict__ W1,
                             const float* __restrict__ W2,
                             const float* __restrict__ M,
                             __nv_bfloat16* outHi, __nv_bfloat16* outLo) {
    int mat = blockIdx.x, t = threadIdx.x; // t = output row n
    const float* src = (mat == 0) ? W1 : (mat == 1) ? W2 : M;
    float v[8];
    for (int g = 0; g < 16; g++) {
#pragma unroll
        for (int j = 0; j < 8; j++) v[j] = src[(g * 8 + j) * 128 + t];
        uint4 hi, lo; cvt8(v, hi, lo);
        long off = (long)mat * 16384 + t * 128 + g * 8;
        *(uint4*)&outHi[off] = hi;
        *(uint4*)&outLo[off] = lo;
    }
}

// elementwise bf16 split of relation_param (R stays [f][k] layout)
__global__ void prepR_kernel(const float* __restrict__ R,
                             __nv_bfloat16* outHi, __nv_bfloat16* outLo) {
    long i = (long)(blockIdx.x * blockDim.x + threadIdx.x) * 8;
    if (i >= (long)NREL * 16384) return;
    float v[8];
    float4 a0 = *(const float4*)&R[i];
    float4 a1 = *(const float4*)&R[i + 4];
    v[0]=a0.x; v[1]=a0.y; v[2]=a0.z; v[3]=a0.w;
    v[4]=a1.x; v[5]=a1.y; v[6]=a1.z; v[7]=a1.w;
    uint4 hi, lo; cvt8(v, hi, lo);
    *(uint4*)&outHi[i] = hi;
    *(uint4*)&outLo[i] = lo;
}

// ==================== HMMA GEMM =============================================
// C[rows,128] = A[rows,128] @ Bmath, where smem B holds Bs[n][k] (bf16 hi/lo,
// i.e. Bmath[k][n] = Bs[n][k]).  A is fp32, converted to bf16 hi/lo in-block.
// Output: fp32 C  OR  bf16-split row-major (SoHi/SoLo).
__global__ void __launch_bounds__(256)
gemm_mma(const float* __restrict__ A, long strideA,
         const __nv_bfloat16* __restrict__ Bhi,
         const __nv_bfloat16* __restrict__ Blo, long strideB,
         float* __restrict__ C, long strideC,
         __nv_bfloat16* SoHi, __nv_bfloat16* SoLo, long strideS,
         int rows) {
    extern __shared__ char smem[];
    __nv_bfloat16* sAh = (__nv_bfloat16*)smem;
    __nv_bfloat16* sAl = sAh + 128 * LDT;
    __nv_bfloat16* sBh = sAl + 128 * LDT;
    __nv_bfloat16* sBl = sBh + 128 * LDT;

    int t = threadIdx.x, wid = t >> 5, l = t & 31;
    int batch = blockIdx.y;
    const float* Ab = A + (long)batch * strideA;
    const __nv_bfloat16* Bhb = Bhi + (long)batch * strideB;
    const __nv_bfloat16* Blb = Blo + (long)batch * strideB;
    int row0 = blockIdx.x * 128;

    // ---- stage A (fp32 -> bf16 split) and B (bf16 copy) into padded smem ----
    {
        int rr = t >> 1, hc = (t & 1) * 64;
        int grow = row0 + rr;
        const float* ar = Ab + (long)grow * 128 + hc;
        float v[8];
#pragma unroll
        for (int g = 0; g < 8; g++) {
            if (grow < rows) {
                float4 a0 = *(const float4*)&ar[g * 8];
                float4 a1 = *(const float4*)&ar[g * 8 + 4];
                v[0]=a0.x; v[1]=a0.y; v[2]=a0.z; v[3]=a0.w;
                v[4]=a1.x; v[5]=a1.y; v[6]=a1.z; v[7]=a1.w;
            } else {
#pragma unroll
                for (int j = 0; j < 8; j++) v[j] = 0.f;
            }
            uint4 hi, lo; cvt8(v, hi, lo);
            int so = rr * LDT + hc + g * 8;
            *(uint4*)&sAh[so] = hi;
            *(uint4*)&sAl[so] = lo;
        }
#pragma unroll
        for (int g = 0; g < 8; g++) {
            long goff = (long)rr * 128 + hc + g * 8;
            int so = rr * LDT + hc + g * 8;
            *(uint4*)&sBh[so] = *(const uint4*)&Bhb[goff];
            *(uint4*)&sBl[so] = *(const uint4*)&Blb[goff];
        }
    }
    __syncthreads();

    uint32_t sAh_u = smem_u32(sAh), sAl_u = smem_u32(sAl);
    uint32_t sBh_u = smem_u32(sBh), sBl_u = smem_u32(sBl);

    int wm = wid >> 2, wn = wid & 3;
    int m0 = wm * 64, n0 = wn * 32;
    int arow = l & 15, acol8 = (l >> 4) * 8;
    int brow = (l & 7) + (l >> 4) * 8, bcol = ((l >> 3) & 1) * 8;

    float acc[4][4][4];
#pragma unroll
    for (int mf = 0; mf < 4; mf++)
#pragma unroll
        for (int nf = 0; nf < 4; nf++)
#pragma unroll
            for (int c = 0; c < 4; c++) acc[mf][nf][c] = 0.f;

#pragma unroll
    for (int ks = 0; ks < 8; ks++) {
        int k0 = ks * 16;
        uint32_t ah[4][4], al[4][4], bh[2][4], bl[2][4];
#pragma unroll
        for (int mf = 0; mf < 4; mf++) {
            uint32_t off = (uint32_t)(((m0 + mf * 16 + arow) * LDT + k0 + acol8) * 2);
            ldm_x4(ah[mf], sAh_u + off);
            ldm_x4(al[mf], sAl_u + off);
        }
#pragma unroll
        for (int nh = 0; nh < 2; nh++) {
            uint32_t off = (uint32_t)(((n0 + nh * 16 + brow) * LDT + k0 + bcol) * 2);
            ldm_x4(bh[nh], sBh_u + off);
            ldm_x4(bl[nh], sBl_u + off);
        }
#pragma unroll
        for (int mf = 0; mf < 4; mf++)
#pragma unroll
            for (int nf = 0; nf < 4; nf++) {
                const uint32_t* bhp = &bh[nf >> 1][(nf & 1) * 2];
                const uint32_t* blp = &bl[nf >> 1][(nf & 1) * 2];
                mma16816(acc[mf][nf], ah[mf], bhp);
                mma16816(acc[mf][nf], ah[mf], blp);
                mma16816(acc[mf][nf], al[mf], bhp);
            }
    }

    // ---- epilogue ----
    int r01 = l >> 2, cql = (l & 3) * 2;
    if (SoHi) {
        __nv_bfloat16* oh = SoHi + (long)batch * strideS;
        __nv_bfloat16* ol = SoLo + (long)batch * strideS;
#pragma unroll
        for (int mf = 0; mf < 4; mf++) {
            int ra = m0 + mf * 16 + r01, rb = ra + 8;
#pragma unroll
            for (int nf = 0; nf < 4; nf++) {
                int col = n0 + nf * 8 + cql;
                uint32_t hi, lo;
                cvt2(acc[mf][nf][0], acc[mf][nf][1], hi, lo);
                *(uint32_t*)&oh[ra * 128 + col] = hi;
                *(uint32_t*)&ol[ra * 128 + col] = lo;
                cvt2(acc[mf][nf][2], acc[mf][nf][3], hi, lo);
                *(uint32_t*)&oh[rb * 128 + col] = hi;
                *(uint32_t*)&ol[rb * 128 + col] = lo;
            }
        }
    } else {
        float* Cb = C + (long)batch * strideC;
#pragma unroll
        for (int mf = 0; mf < 4; mf++) {
            int ga = row0 + m0 + mf * 16 + r01, gb = ga + 8;
#pragma unroll
            for (int nf = 0; nf < 4; nf++) {
                int col = n0 + nf * 8 + cql;
                if (ga < rows) {
                    float2 v = make_float2(acc[mf][nf][0], acc[mf][nf][1]);
                    *(float2*)&Cb[(long)ga * 128 + col] = v;
                }
                if (gb < rows) {
                    float2 v = make_float2(acc[mf][nf][2], acc[mf][nf][3]);
                    *(float2*)&Cb[(long)gb * 128 + col] = v;
                }
            }
        }
    }
}

// ==================== aggregation ===========================================
// out[d] = dinv[d] * ( sum_s dinv[s]*h[s] + dinv[d]*h[d] ) + b
// (both degree scales applied here so GEMMs are independent of the CSR branch)
__global__ void agg_kernel(const float* __restrict__ h,
                           const int* __restrict__ rowptr,
                           const int* __restrict__ col,
                           const float* __restrict__ dinv,
                           const float* __restrict__ bias,
                           float* __restrict__ out, int n) {
    int warp = (blockIdx.x * blockDim.x + threadIdx.x) >> 5;
    int lane = threadIdx.x & 31;
    if (warp >= n) return;
    int beg = rowptr[warp], end = rowptr[warp + 1];
    float dv = dinv[warp];

    float4 self = *(const float4*)&h[(long)warp * 128 + lane * 4];
    float4 acc = make_float4(dv * self.x, dv * self.y, dv * self.z, dv * self.w);

    int e = beg;
    for (; e + 4 <= end; e += 4) {
        int s0 = col[e], s1 = col[e + 1], s2 = col[e + 2], s3 = col[e + 3];
        float w0 = dinv[s0], w1 = dinv[s1], w2 = dinv[s2], w3 = dinv[s3];
        float4 v0 = *(const float4*)&h[(long)s0 * 128 + lane * 4];
        float4 v1 = *(const float4*)&h[(long)s1 * 128 + lane * 4];
        float4 v2 = *(const float4*)&h[(long)s2 * 128 + lane * 4];
        float4 v3 = *(const float4*)&h[(long)s3 * 128 + lane * 4];
        acc.x = fmaf(w0, v0.x, fmaf(w1, v1.x, fmaf(w2, v2.x, fmaf(w3, v3.x, acc.x))));
        acc.y = fmaf(w0, v0.y, fmaf(w1, v1.y, fmaf(w2, v2.y, fmaf(w3, v3.y, acc.y))));
        acc.z = fmaf(w0, v0.z, fmaf(w1, v1.z, fmaf(w2, v2.z, fmaf(w3, v3.z, acc.z))));
        acc.w = fmaf(w0, v0.w, fmaf(w1, v1.w, fmaf(w2, v2.w, fmaf(w3, v3.w, acc.w))));
    }
    for (; e < end; e++) {
        int s = col[e];
        float w = dinv[s];
        float4 v = *(const float4*)&h[(long)s * 128 + lane * 4];
        acc.x = fmaf(w, v.x, acc.x);
        acc.y = fmaf(w, v.y, acc.y);
        acc.z = fmaf(w, v.z, acc.z);
        acc.w = fmaf(w, v.w, acc.w);
    }
    float4 bb = *(const float4*)&bias[lane * 4];
    *(float4*)&out[(long)warp * 128 + lane * 4] =
        make_float4(acc.x * dv + bb.x, acc.y * dv + bb.y,
                    acc.z * dv + bb.z, acc.w * dv + bb.w);
}

// ==================== gather batch embeddings ===============================
__global__ void gather_kernel(const float* __restrict__ x,
                              const int* __restrict__ head,
                              const int* __restrict__ tail,
                              float* __restrict__ Hg,
                              __nv_bfloat16* Thi, __nv_bfloat16* Tlo) {
    int b = blockIdx.x * 128 + threadIdx.x;
    const float4* hr = (const float4*)(x + (long)head[b] * 128);
    float4* ho = (float4*)(Hg + (long)b * 128);
#pragma unroll 8
    for (int j = 0; j < 32; j++) ho[j] = hr[j];

    const float* tr = x + (long)tail[b] * 128;
    float v[8];
#pragma unroll
    for (int g = 0; g < 16; g++) {
        float4 a0 = *(const float4*)&tr[g * 8];
        float4 a1 = *(const float4*)&tr[g * 8 + 4];
        v[0]=a0.x; v[1]=a0.y; v[2]=a0.z; v[3]=a0.w;
        v[4]=a1.x; v[5]=a1.y; v[6]=a1.z; v[7]=a1.w;
        uint4 hi, lo; cvt8(v, hi, lo);
        long off = (long)b * 128 + g * 8;
        *(uint4*)&Thi[off] = hi;
        *(uint4*)&Tlo[off] = lo;
    }
}

// ==================== scorer ================================================
__global__ void __launch_bounds__(256)
score_mma(const __nv_bfloat16* __restrict__ Thi,
          const __nv_bfloat16* __restrict__ Tlo,
          const __nv_bfloat16* __restrict__ Shi,
          const __nv_bfloat16* __restrict__ Slo,
          const float* __restrict__ Hg, float* __restrict__ out) {
    extern __shared__ char smem[];
    __nv_bfloat16* sAh = (__nv_bfloat16*)smem;
    __nv_bfloat16* sAl = sAh + 128 * LDT;
    __nv_bfloat16* sBh = sAl + 128 * LDT;
    __nv_bfloat16* sBl = sBh + 128 * LDT;
    float* Hs = (float*)(sBl + 128 * LDT);       // [128][LDH]
    float* out_s = Hs + 128 * LDH;               // [128]

    int t = threadIdx.x, wid = t >> 5, l = t & 31;
    int tile = blockIdx.x, rpair = blockIdx.y;
    int rr = t >> 1, hc = (t & 1) * 64;

    // stage tail tile + head tile
    {
        long base = (long)(tile * 128 + rr) * 128 + hc;
#pragma unroll
        for (int g = 0; g < 8; g++) {
            int so = rr * LDT + hc + g * 8;
            *(uint4*)&sAh[so] = *(const uint4*)&Thi[base + g * 8];
            *(uint4*)&sAl[so] = *(const uint4*)&Tlo[base + g * 8];
        }
        const float* hr = Hg + (long)(tile * 128 + rr) * 128 + hc;
#pragma unroll
        for (int g = 0; g < 8; g++) {
            float4 v0 = *(const float4*)&hr[g * 8];
            float4 v1 = *(const float4*)&hr[g * 8 + 4];
            int so = rr * LDH + hc + g * 8;
            *(float4*)&Hs[so] = v0;
            *(float4*)&Hs[so + 4] = v1;
        }
    }

    uint32_t sAh_u = smem_u32(sAh), sAl_u = smem_u32(sAl);
    uint32_t sBh_u = smem_u32(sBh), sBl_u = smem_u32(sBl);

    int wm = wid >> 2, wn = wid & 3;
    int m0 = wm * 64, n0 = wn * 32;
    int arow = l & 15, acol8 = (l >> 4) * 8;
    int brow = (l & 7) + (l >> 4) * 8, bcol = ((l >> 3) & 1) * 8;
    int r01 = l >> 2, cql = (l & 3) * 2;

    for (int i = 0; i < 2; i++) {
        int r = rpair * 2 + i;
        __syncthreads();   // protect B smem + out_s from prior readers
        // stage S_r
        {
            long base = (long)r * 16384 + rr * 128 + hc;
#pragma unroll
            for (int g = 0; g < 8; g++) {
                int so = rr * LDT + hc + g * 8;
                *(uint4*)&sBh[so] = *(const uint4*)&Shi[base + g * 8];
                *(uint4*)&sBl[so] = *(const uint4*)&Slo[base + g * 8];
            }
        }
        if (t < 128) out_s[t] = 0.f;
        __syncthreads();

        float acc[4][4][4];
#pragma unroll
        for (int mf = 0; mf < 4; mf++)
#pragma unroll
            for (int nf = 0; nf < 4; nf++)
#pragma unroll
                for (int c = 0; c < 4; c++) acc[mf][nf][c] = 0.f;

#pragma unroll
        for (int ks = 0; ks < 8; ks++) {
            int k0 = ks * 16;
            uint32_t ah[4][4], al[4][4], bh[2][4], bl[2][4];
#pragma unroll
            for (int mf = 0; mf < 4; mf++) {
                uint32_t off = (uint32_t)(((m0 + mf * 16 + arow) * LDT + k0 + acol8) * 2);
                ldm_x4(ah[mf], sAh_u + off);
                ldm_x4(al[mf], sAl_u + off);
            }
#pragma unroll
            for (int nh = 0; nh < 2; nh++) {
                uint32_t off = (uint32_t)(((n0 + nh * 16 + brow) * LDT + k0 + bcol) * 2);
                ldm_x4(bh[nh], sBh_u + off);
                ldm_x4(bl[nh], sBl_u + off);
            }
#pragma unroll
            for (int mf = 0; mf < 4; mf++)
#pragma unroll
                for (int nf = 0; nf < 4; nf++) {
                    const uint32_t* bhp = &bh[nf >> 1][(nf & 1) * 2];
                    const uint32_t* blp = &bl[nf >> 1][(nf & 1) * 2];
                    mma16816(acc[mf][nf], ah[mf], bhp);
                    mma16816(acc[mf][nf], ah[mf], blp);
                    mma16816(acc[mf][nf], al[mf], bhp);
                }
        }

        // fragment-local dot with head
        float part[4][2];
#pragma unroll
        for (int mf = 0; mf < 4; mf++) { part[mf][0] = 0.f; part[mf][1] = 0.f; }
#pragma unroll
        for (int mf = 0; mf < 4; mf++) {
            int ra = m0 + mf * 16 + r01;
#pragma unroll
            for (int nf = 0; nf < 4; nf++) {
                int col = n0 + nf * 8 + cql;
                float2 h0 = *(float2*)&Hs[ra * LDH + col];
                float2 h1 = *(float2*)&Hs[(ra + 8) * LDH + col];
                part[mf][0] += acc[mf][nf][0] * h0.x + acc[mf][nf][1] * h0.y;
                part[mf][1] += acc[mf][nf][2] * h1.x + acc[mf][nf][3] * h1.y;
            }
        }
#pragma unroll
        for (int mf = 0; mf < 4; mf++) {
#pragma unroll
            for (int hh = 0; hh < 2; hh++) {
                part[mf][hh] += __shfl_xor_sync(0xffffffffu, part[mf][hh], 1);
                part[mf][hh] += __shfl_xor_sync(0xffffffffu, part[mf][hh], 2);
            }
        }
        if ((l & 3) == 0) {
#pragma unroll
            for (int mf = 0; mf < 4; mf++) {
                atomicAdd(&out_s[m0 + mf * 16 + r01], part[mf][0]);
                atomicAdd(&out_s[m0 + mf * 16 + r01 + 8], part[mf][1]);
            }
        }
        __syncthreads();
        if (t < 128)
            out[(long)(tile * 128 + t) * NREL + r] = out_s[t];
    }
}

// ==================== launch ================================================
extern "C" void kernel_launch(void* const* d_in, const int* in_sizes, int n_in,
                              void* d_out, int out_size) {
    const float* init_emb = (const float*)d_in[0];
    const float* W1       = (const float*)d_in[1];
    const float* b1       = (const float*)d_in[2];
    const float* W2       = (const float*)d_in[3];
    const float* b2       = (const float*)d_in[4];
    const float* Rp       = (const float*)d_in[5];
    const float* Mp       = (const float*)d_in[6];
    const int*   head     = (const int*)d_in[7];
    const int*   tail     = (const int*)d_in[8];
    const int*   ei       = (const int*)d_in[9];
    float* out = (float*)d_out;

    const int* src = ei;
    const int* dst = ei + NEDGES;

    float *p_h, *p_x1, *p_x2, *p_dinv, *p_T, *p_head;
    __nv_bfloat16 *p_WThi, *p_WTlo, *p_Rhi, *p_Rlo, *p_Shi, *p_Slo, *p_thi, *p_tlo;
    int *p_cnt, *p_rowptr, *p_cur, *p_col;
    cudaGetSymbolAddress((void**)&p_h, g_h);
    cudaGetSymbolAddress((void**)&p_x1, g_x1);
    cudaGetSymbolAddress((void**)&p_x2, g_x2);
    cudaGetSymbolAddress((void**)&p_dinv, g_dinv);
    cudaGetSymbolAddress((void**)&p_cnt, g_cnt);
    cudaGetSymbolAddress((void**)&p_rowptr, g_rowptr);
    cudaGetSymbolAddress((void**)&p_cur, g_cur);
    cudaGetSymbolAddress((void**)&p_col, g_col);
    cudaGetSymbolAddress((void**)&p_T, g_T);
    cudaGetSymbolAddress((void**)&p_WThi, g_WThi);
    cudaGetSymbolAddress((void**)&p_WTlo, g_WTlo);
    cudaGetSymbolAddress((void**)&p_Rhi, g_Rhi);
    cudaGetSymbolAddress((void**)&p_Rlo, g_Rlo);
    cudaGetSymbolAddress((void**)&p_Shi, g_Shi);
    cudaGetSymbolAddress((void**)&p_Slo, g_Slo);
    cudaGetSymbolAddress((void**)&p_head, g_head);
    cudaGetSymbolAddress((void**)&p_thi, g_thi);
    cudaGetSymbolAddress((void**)&p_tlo, g_tlo);

    const int GEMM_SMEM  = 4 * 128 * LDT * 2;                       // 139264
    const int SCORE_SMEM = GEMM_SMEM + 128 * LDH * 4 + 128 * 4;     // 207360
    cudaFuncSetAttribute(gemm_mma,  cudaFuncAttributeMaxDynamicSharedMemorySize, GEMM_SMEM);
    cudaFuncSetAttribute(score_mma, cudaFuncAttributeMaxDynamicSharedMemorySize, SCORE_SMEM);

    // ---- fork/join streams for capture-parallel branches ----
    cudaStream_t sB, sC;
    cudaStreamCreateWithFlags(&sB, cudaStreamNonBlocking);
    cudaStreamCreateWithFlags(&sC, cudaStreamNonBlocking);
    cudaEvent_t evRoot, evW, evCSR, evS;
    cudaEventCreateWithFlags(&evRoot, cudaEventDisableTiming);
    cudaEventCreateWithFlags(&evW,    cudaEventDisableTiming);
    cudaEventCreateWithFlags(&evCSR,  cudaEventDisableTiming);
    cudaEventCreateWithFlags(&evS,    cudaEventDisableTiming);

    cudaEventRecord(evRoot, 0);

    // --- branch B: CSR build (independent of node chain until agg1) ---
    cudaStreamWaitEvent(sB, evRoot, 0);
    zero_cnt_kernel<<<(NNODES + 255) / 256, 256, 0, sB>>>(p_cnt, NNODES);
    count_kernel<<<(NEDGES / 4 + 255) / 256, 256, 0, sB>>>(
        (const int4*)dst, p_cnt, NEDGES / 4);
    scan_kernel<<<1, 1024, 0, sB>>>(p_cnt, p_rowptr, p_cur, p_dinv, NNODES);
    fill_kernel<<<(NEDGES / 4 + 255) / 256, 256, 0, sB>>>(
        (const int4*)src, (const int4*)dst, p_cur, p_col, NEDGES / 4);
    cudaEventRecord(evCSR, sB);

    // --- main: weight prep (needed by gemm1 and by branch C's T-GEMM) ---
    prepW_kernel<<<3, 128>>>(W1, W2, Mp, p_WThi, p_WTlo);
    cudaEventRecord(evW, 0);

    // --- branch C: relation prep + S precompute ---
    cudaStreamWaitEvent(sC, evRoot, 0);
    prepR_kernel<<<(NREL * 16384 / 8 + 255) / 256, 256, 0, sC>>>(Rp, p_Rhi, p_Rlo);
    cudaStreamWaitEvent(sC, evW, 0);
    gemm_mma<<<dim3(1, NREL), 256, GEMM_SMEM, sC>>>(
        Rp, 16384, p_WThi + 2 * 16384, p_WTlo + 2 * 16384,  0,
        p_T, 16384, nullptr, nullptr, 0, 128);
    gemm_mma<<<dim3(1, NREL), 256, GEMM_SMEM, sC>>>(
        p_T, 16384, p_Rhi, p_Rlo, 16384,
        nullptr, 0, p_Shi, p_Slo, 16384, 128);
    cudaEventRecord(evS, sC);

    int ntiles = (NNODES + 127) / 128;  // 391
    int agg_blocks = (NNODES * 32 + 255) / 256;

    // --- main chain (GEMMs no longer touch dinv; only agg waits on CSR) ---
    gemm_mma<<<dim3(ntiles, 1), 256, GEMM_SMEM>>>(
        init_emb, 0, p_WThi, p_WTlo, 0, p_h, 0,
        nullptr, nullptr, 0, NNODES);
    cudaStreamWaitEvent(0, evCSR, 0);
    agg_kernel<<<agg_blocks, 256>>>(p_h, p_rowptr, p_col, p_dinv, b1, p_x1, NNODES);
    gemm_mma<<<dim3(ntiles, 1), 256, GEMM_SMEM>>>(
        p_x1, 0, p_WThi + 16384, p_WTlo + 16384, 0, p_h, 0,
        nullptr, nullptr, 0, NNODES);
    agg_kernel<<<agg_blocks, 256>>>(p_h, p_rowptr, p_col, p_dinv, b2, p_x2, NNODES);

    gather_kernel<<<NBATCH / 128, 128>>>(p_x2, head, tail, p_head, p_thi, p_tlo);

    cudaStreamWaitEvent(0, evS, 0);
    score_mma<<<dim3(NBATCH / 128, NREL / 2), 256, SCORE_SMEM>>>(
        p_thi, p_tlo, p_Shi, p_Slo, p_head, out);

    cudaStreamDestroy(sB);
    cudaStreamDestroy(sC);
    cudaEventDestroy(evRoot);
    cudaEventDestroy(evW);
    cudaEventDestroy(evCSR);
    cudaEventDestroy(evS);
}

// round 6
// speedup vs baseline: 2.0915x; 1.1375x over previous
#include <cuda_runtime.h>
#include <cuda_fp16.h>
#include <cstdint>
#include <math.h>

#define NNODES 50000
#define NEDGES 800000
#define DIM    128
#define NREL   86
#define NBATCH 2048
#define LDT    136   // fp16 smem stride (elems)
#define LDH    132   // fp32 head smem stride (elems)

// ---------------- scratch (device globals; no allocation allowed) ------------
__device__ float g_h  [NNODES * DIM];
__device__ float g_x1 [NNODES * DIM];
__device__ float g_x2 [NNODES * DIM];
__device__ float g_dinv[NNODES];
__device__ int   g_cnt [NNODES];
__device__ int   g_rowptr[NNODES + 1];
__device__ int   g_cur [NNODES];
__device__ int   g_col [NEDGES];
__device__ float g_T   [NREL * DIM * DIM];
__device__ __half g_WTh[3 * DIM * DIM];     // W1^T, W2^T, M^T  (single fp16)
__device__ __half g_Rh [NREL * DIM * DIM];  // R (single fp16, [f][k] layout)
__device__ __half g_Sh [NREL * DIM * DIM];  // S (single fp16)
__device__ float g_head[NBATCH * DIM];
__device__ __half g_thi[NBATCH * DIM];      // tail hi (fp16 split)
__device__ __half g_tlo[NBATCH * DIM];      // tail lo

// ==================== helpers ===============================================
__device__ __forceinline__ uint32_t smem_u32(const void* p) {
    uint32_t a;
    asm("{ .reg .u64 t; cvta.to.shared.u64 t, %1; cvt.u32.u64 %0, t; }"
        : "=r"(a) : "l"(p));
    return a;
}

__device__ __forceinline__ void ldm_x4(uint32_t* r, uint32_t addr) {
    asm volatile("ldmatrix.sync.aligned.m8n8.x4.shared.b16 {%0,%1,%2,%3}, [%4];"
                 : "=r"(r[0]), "=r"(r[1]), "=r"(r[2]), "=r"(r[3]) : "r"(addr));
}

__device__ __forceinline__ void mma16816(float* d, const uint32_t* a,
                                         const uint32_t* b) {
    asm volatile(
        "mma.sync.aligned.m16n8k16.row.col.f32.f16.f16.f32 "
        "{%0,%1,%2,%3}, {%4,%5,%6,%7}, {%8,%9}, {%0,%1,%2,%3};"
        : "+f"(d[0]), "+f"(d[1]), "+f"(d[2]), "+f"(d[3])
        : "r"(a[0]), "r"(a[1]), "r"(a[2]), "r"(a[3]), "r"(b[0]), "r"(b[1]));
}

// split two fp32 -> packed fp16x2 hi + lo (A-side: ~exact 2-term repr)
__device__ __forceinline__ void hcvt2(float a, float b, uint32_t& hi, uint32_t& lo) {
    __half2 h = __floats2half2_rn(a, b);
    float ra = a - __half2float(__low2half(h));
    float rb = b - __half2float(__high2half(h));
    __half2 l = __floats2half2_rn(ra, rb);
    hi = *(uint32_t*)&h;
    lo = *(uint32_t*)&l;
}
__device__ __forceinline__ void hcvt8(const float* v, uint4& hi, uint4& lo) {
    uint32_t h[4], l[4];
#pragma unroll
    for (int i = 0; i < 4; i++) hcvt2(v[2 * i], v[2 * i + 1], h[i], l[i]);
    hi = make_uint4(h[0], h[1], h[2], h[3]);
    lo = make_uint4(l[0], l[1], l[2], l[3]);
}
// single-round 8 fp32 -> 8 fp16 (B-side)
__device__ __forceinline__ uint4 hcvt8s(const float* v) {
    uint32_t h[4];
#pragma unroll
    for (int i = 0; i < 4; i++) {
        __half2 p = __floats2half2_rn(v[2 * i], v[2 * i + 1]);
        h[i] = *(uint32_t*)&p;
    }
    return make_uint4(h[0], h[1], h[2], h[3]);
}

// ==================== CSR build =============================================
__global__ void zero_cnt_kernel(int* cnt, int n) {
    int i = blockIdx.x * blockDim.x + threadIdx.x;
    if (i < n) cnt[i] = 0;
}
__global__ void count_kernel(const int4* __restrict__ dst4, int* cnt, int e4) {
    int i = blockIdx.x * blockDim.x + threadIdx.x;
    if (i < e4) {
        int4 d = dst4[i];
        atomicAdd(&cnt[d.x], 1);
        atomicAdd(&cnt[d.y], 1);
        atomicAdd(&cnt[d.z], 1);
        atomicAdd(&cnt[d.w], 1);
    }
}
__global__ void scan_kernel(const int* __restrict__ cnt, int* rowptr, int* cur,
                            float* dinv, int n) {
    __shared__ int ssum[1024];
    int t = threadIdx.x;
    int chunk = (n + 1023) / 1024;
    int beg = t * chunk, end = min(beg + chunk, n);
    int s = 0;
    for (int i = beg; i < end; i++) s += cnt[i];
    ssum[t] = s;
    __syncthreads();
    for (int off = 1; off < 1024; off <<= 1) {
        int v = (t >= off) ? ssum[t - off] : 0;
        __syncthreads();
        ssum[t] += v;
        __syncthreads();
    }
    int base = (t == 0) ? 0 : ssum[t - 1];
    for (int i = beg; i < end; i++) {
        rowptr[i] = base; cur[i] = base;
        dinv[i] = rsqrtf((float)(cnt[i] + 1));
        base += cnt[i];
    }
    if (t == 1023) rowptr[n] = ssum[1023];
}
__global__ void fill_kernel(const int4* __restrict__ src4,
                            const int4* __restrict__ dst4,
                            int* cur, int* col, int e4) {
    int i = blockIdx.x * blockDim.x + threadIdx.x;
    if (i < e4) {
        int4 d = dst4[i];
        int4 s = src4[i];
        col[atomicAdd(&cur[d.x], 1)] = s.x;
        col[atomicAdd(&cur[d.y], 1)] = s.y;
        col[atomicAdd(&cur[d.z], 1)] = s.z;
        col[atomicAdd(&cur[d.w], 1)] = s.w;
    }
}

// ==================== operand prep ==========================================
// transpose W1, W2, M into [n][k] layout, single fp16
__global__ void prepW_kernel(const float* __restrict__ W1,
                             const float* __restrict__ W2,
                             const float* __restrict__ M,
                             __half* outH) {
    int mat = blockIdx.x, t = threadIdx.x; // t = output row n
    const float* src = (mat == 0) ? W1 : (mat == 1) ? W2 : M;
    float v[8];
    for (int g = 0; g < 16; g++) {
#pragma unroll
        for (int j = 0; j < 8; j++) v[j] = src[(g * 8 + j) * 128 + t];
        long off = (long)mat * 16384 + t * 128 + g * 8;
        *(uint4*)&outH[off] = hcvt8s(v);
    }
}

// elementwise fp16 round of relation_param (R stays [f][k] layout)
__global__ void prepR_kernel(const float* __restrict__ R, __half* outH) {
    long i = (long)(blockIdx.x * blockDim.x + threadIdx.x) * 8;
    if (i >= (long)NREL * 16384) return;
    float v[8];
    float4 a0 = *(const float4*)&R[i];
    float4 a1 = *(const float4*)&R[i + 4];
    v[0]=a0.x; v[1]=a0.y; v[2]=a0.z; v[3]=a0.w;
    v[4]=a1.x; v[5]=a1.y; v[6]=a1.z; v[7]=a1.w;
    *(uint4*)&outH[i] = hcvt8s(v);
}

// ==================== HMMA GEMM (fp16 2-pass) ================================
// C[rows,128] = A[rows,128] @ Bmath, smem B holds Bs[n][k] single fp16
// (Bmath[k][n] = Bs[n][k]).  A fp32 -> exact fp16 hi/lo split in-block.
// Output: fp32 C  OR  single-fp16 row-major (So).
__global__ void __launch_bounds__(256)
gemm_mma(const float* __restrict__ A, long strideA,
         const __half* __restrict__ Bh, long strideB,
         float* __restrict__ C, long strideC,
         __half* So, long strideS,
         int rows) {
    extern __shared__ char smem[];
    __half* sAh = (__half*)smem;
    __half* sAl = sAh + 128 * LDT;
    __half* sB  = sAl + 128 * LDT;

    int t = threadIdx.x, wid = t >> 5, l = t & 31;
    int batch = blockIdx.y;
    const float* Ab = A + (long)batch * strideA;
    const __half* Bb = Bh + (long)batch * strideB;
    int row0 = blockIdx.x * 128;

    // ---- stage A (fp32 -> fp16 split) and B (fp16 copy) into padded smem ----
    {
        int rr = t >> 1, hc = (t & 1) * 64;
        int grow = row0 + rr;
        const float* ar = Ab + (long)grow * 128 + hc;
        float v[8];
#pragma unroll
        for (int g = 0; g < 8; g++) {
            if (grow < rows) {
                float4 a0 = *(const float4*)&ar[g * 8];
                float4 a1 = *(const float4*)&ar[g * 8 + 4];
                v[0]=a0.x; v[1]=a0.y; v[2]=a0.z; v[3]=a0.w;
                v[4]=a1.x; v[5]=a1.y; v[6]=a1.z; v[7]=a1.w;
            } else {
#pragma unroll
                for (int j = 0; j < 8; j++) v[j] = 0.f;
            }
            uint4 hi, lo; hcvt8(v, hi, lo);
            int so = rr * LDT + hc + g * 8;
            *(uint4*)&sAh[so] = hi;
            *(uint4*)&sAl[so] = lo;
        }
#pragma unroll
        for (int g = 0; g < 8; g++) {
            long goff = (long)rr * 128 + hc + g * 8;
            int so = rr * LDT + hc + g * 8;
            *(uint4*)&sB[so] = *(const uint4*)&Bb[goff];
        }
    }
    __syncthreads();

    uint32_t sAh_u = smem_u32(sAh), sAl_u = smem_u32(sAl);
    uint32_t sB_u = smem_u32(sB);

    int wm = wid >> 2, wn = wid & 3;
    int m0 = wm * 64, n0 = wn * 32;
    int arow = l & 15, acol8 = (l >> 4) * 8;
    int brow = (l & 7) + (l >> 4) * 8, bcol = ((l >> 3) & 1) * 8;

    float acc[4][4][4];
#pragma unroll
    for (int mf = 0; mf < 4; mf++)
#pragma unroll
        for (int nf = 0; nf < 4; nf++)
#pragma unroll
            for (int c = 0; c < 4; c++) acc[mf][nf][c] = 0.f;

#pragma unroll
    for (int ks = 0; ks < 8; ks++) {
        int k0 = ks * 16;
        uint32_t ah[4][4], al[4][4], bf[2][4];
#pragma unroll
        for (int mf = 0; mf < 4; mf++) {
            uint32_t off = (uint32_t)(((m0 + mf * 16 + arow) * LDT + k0 + acol8) * 2);
            ldm_x4(ah[mf], sAh_u + off);
            ldm_x4(al[mf], sAl_u + off);
        }
#pragma unroll
        for (int nh = 0; nh < 2; nh++) {
            uint32_t off = (uint32_t)(((n0 + nh * 16 + brow) * LDT + k0 + bcol) * 2);
            ldm_x4(bf[nh], sB_u + off);
        }
#pragma unroll
        for (int mf = 0; mf < 4; mf++)
#pragma unroll
            for (int nf = 0; nf < 4; nf++) {
                const uint32_t* bp = &bf[nf >> 1][(nf & 1) * 2];
                mma16816(acc[mf][nf], ah[mf], bp);
                mma16816(acc[mf][nf], al[mf], bp);
            }
    }

    // ---- epilogue ----
    int r01 = l >> 2, cql = (l & 3) * 2;
    if (So) {
        __half* oh = So + (long)batch * strideS;
#pragma unroll
        for (int mf = 0; mf < 4; mf++) {
            int ra = m0 + mf * 16 + r01, rb = ra + 8;
#pragma unroll
            for (int nf = 0; nf < 4; nf++) {
                int col = n0 + nf * 8 + cql;
                __half2 p0 = __floats2half2_rn(acc[mf][nf][0], acc[mf][nf][1]);
                __half2 p1 = __floats2half2_rn(acc[mf][nf][2], acc[mf][nf][3]);
                *(uint32_t*)&oh[ra * 128 + col] = *(uint32_t*)&p0;
                *(uint32_t*)&oh[rb * 128 + col] = *(uint32_t*)&p1;
            }
        }
    } else {
        float* Cb = C + (long)batch * strideC;
#pragma unroll
        for (int mf = 0; mf < 4; mf++) {
            int ga = row0 + m0 + mf * 16 + r01, gb = ga + 8;
#pragma unroll
            for (int nf = 0; nf < 4; nf++) {
                int col = n0 + nf * 8 + cql;
                if (ga < rows) {
                    float2 v = make_float2(acc[mf][nf][0], acc[mf][nf][1]);
                    *(float2*)&Cb[(long)ga * 128 + col] = v;
                }
                if (gb < rows) {
                    float2 v = make_float2(acc[mf][nf][2], acc[mf][nf][3]);
                    *(float2*)&Cb[(long)gb * 128 + col] = v;
                }
            }
        }
    }
}

// ==================== aggregation ===========================================
// out[d] = dinv[d] * ( sum_s dinv[s]*h[s] + dinv[d]*h[d] ) + b
__global__ void agg_kernel(const float* __restrict__ h,
                           const int* __restrict__ rowptr,
                           const int* __restrict__ col,
                           const float* __restrict__ dinv,
                           const float* __restrict__ bias,
                           float* __restrict__ out, int n) {
    int warp = (blockIdx.x * blockDim.x + threadIdx.x) >> 5;
    int lane = threadIdx.x & 31;
    if (warp >= n) return;
    int beg = rowptr[warp], end = rowptr[warp + 1];
    float dv = dinv[warp];

    float4 self = *(const float4*)&h[(long)warp * 128 + lane * 4];
    float4 acc = make_float4(dv * self.x, dv * self.y, dv * self.z, dv * self.w);

    int e = beg;
    for (; e + 4 <= end; e += 4) {
        int s0 = col[e], s1 = col[e + 1], s2 = col[e + 2], s3 = col[e + 3];
        float w0 = dinv[s0], w1 = dinv[s1], w2 = dinv[s2], w3 = dinv[s3];
        float4 v0 = *(const float4*)&h[(long)s0 * 128 + lane * 4];
        float4 v1 = *(const float4*)&h[(long)s1 * 128 + lane * 4];
        float4 v2 = *(const float4*)&h[(long)s2 * 128 + lane * 4];
        float4 v3 = *(const float4*)&h[(long)s3 * 128 + lane * 4];
        acc.x = fmaf(w0, v0.x, fmaf(w1, v1.x, fmaf(w2, v2.x, fmaf(w3, v3.x, acc.x))));
        acc.y = fmaf(w0, v0.y, fmaf(w1, v1.y, fmaf(w2, v2.y, fmaf(w3, v3.y, acc.y))));
        acc.z = fmaf(w0, v0.z, fmaf(w1, v1.z, fmaf(w2, v2.z, fmaf(w3, v3.z, acc.z))));
        acc.w = fmaf(w0, v0.w, fmaf(w1, v1.w, fmaf(w2, v2.w, fmaf(w3, v3.w, acc.w))));
    }
    for (; e < end; e++) {
        int s = col[e];
        float w = dinv[s];
        float4 v = *(const float4*)&h[(long)s * 128 + lane * 4];
        acc.x = fmaf(w, v.x, acc.x);
        acc.y = fmaf(w, v.y, acc.y);
        acc.z = fmaf(w, v.z, acc.z);
        acc.w = fmaf(w, v.w, acc.w);
    }
    float4 bb = *(const float4*)&bias[lane * 4];
    *(float4*)&out[(long)warp * 128 + lane * 4] =
        make_float4(acc.x * dv + bb.x, acc.y * dv + bb.y,
                    acc.z * dv + bb.z, acc.w * dv + bb.w);
}

// ==================== gather batch embeddings ===============================
__global__ void gather_kernel(const float* __restrict__ x,
                              const int* __restrict__ head,
                              const int* __restrict__ tail,
                              float* __restrict__ Hg,
                              __half* Thi, __half* Tlo) {
    int b = blockIdx.x * 128 + threadIdx.x;
    const float4* hr = (const float4*)(x + (long)head[b] * 128);
    float4* ho = (float4*)(Hg + (long)b * 128);
#pragma unroll 8
    for (int j = 0; j < 32; j++) ho[j] = hr[j];

    const float* tr = x + (long)tail[b] * 128;
    float v[8];
#pragma unroll
    for (int g = 0; g < 16; g++) {
        float4 a0 = *(const float4*)&tr[g * 8];
        float4 a1 = *(const float4*)&tr[g * 8 + 4];
        v[0]=a0.x; v[1]=a0.y; v[2]=a0.z; v[3]=a0.w;
        v[4]=a1.x; v[5]=a1.y; v[6]=a1.z; v[7]=a1.w;
        uint4 hi, lo; hcvt8(v, hi, lo);
        long off = (long)b * 128 + g * 8;
        *(uint4*)&Thi[off] = hi;
        *(uint4*)&Tlo[off] = lo;
    }
}

// ==================== scorer ================================================
// block = (batch tile of 128) x (pair of relations).
// P2[b,e] = sum_f tail[b,f] * S_r[e,f]  (HMMA fp16 2-pass)
// out[b,r] = sum_e P2[b,e] * head[b,e]  (fp32, fragment-local)
__global__ void __launch_bounds__(256)
score_mma(const __half* __restrict__ Thi,
          const __half* __restrict__ Tlo,
          const __half* __restrict__ Sh,
          const float* __restrict__ Hg, float* __restrict__ out) {
    extern __shared__ char smem[];
    __half* sAh = (__half*)smem;
    __half* sAl = sAh + 128 * LDT;
    __half* sB  = sAl + 128 * LDT;
    float* Hs = (float*)(sB + 128 * LDT);        // [128][LDH]
    float* out_s = Hs + 128 * LDH;               // [128]

    int t = threadIdx.x, wid = t >> 5, l = t & 31;
    int tile = blockIdx.x, rpair = blockIdx.y;
    int rr = t >> 1, hc = (t & 1) * 64;

    // stage tail tile + head tile
    {
        long base = (long)(tile * 128 + rr) * 128 + hc;
#pragma unroll
        for (int g = 0; g < 8; g++) {
            int so = rr * LDT + hc + g * 8;
            *(uint4*)&sAh[so] = *(const uint4*)&Thi[base + g * 8];
            *(uint4*)&sAl[so] = *(const uint4*)&Tlo[base + g * 8];
        }
        const float* hr = Hg + (long)(tile * 128 + rr) * 128 + hc;
#pragma unroll
        for (int g = 0; g < 8; g++) {
            float4 v0 = *(const float4*)&hr[g * 8];
            float4 v1 = *(const float4*)&hr[g * 8 + 4];
            int so = rr * LDH + hc + g * 8;
            *(float4*)&Hs[so] = v0;
            *(float4*)&Hs[so + 4] = v1;
        }
    }

    uint32_t sAh_u = smem_u32(sAh), sAl_u = smem_u32(sAl);
    uint32_t sB_u = smem_u32(sB);

    int wm = wid >> 2, wn = wid & 3;
    int m0 = wm * 64, n0 = wn * 32;
    int arow = l & 15, acol8 = (l >> 4) * 8;
    int brow = (l & 7) + (l >> 4) * 8, bcol = ((l >> 3) & 1) * 8;
    int r01 = l >> 2, cql = (l & 3) * 2;

    for (int i = 0; i < 2; i++) {
        int r = rpair * 2 + i;
        __syncthreads();   // protect B smem + out_s from prior readers
        // stage S_r (single fp16)
        {
            long base = (long)r * 16384 + rr * 128 + hc;
#pragma unroll
            for (int g = 0; g < 8; g++) {
                int so = rr * LDT + hc + g * 8;
                *(uint4*)&sB[so] = *(const uint4*)&Sh[base + g * 8];
            }
        }
        if (t < 128) out_s[t] = 0.f;
        __syncthreads();

        float acc[4][4][4];
#pragma unroll
        for (int mf = 0; mf < 4; mf++)
#pragma unroll
            for (int nf = 0; nf < 4; nf++)
#pragma unroll
                for (int c = 0; c < 4; c++) acc[mf][nf][c] = 0.f;

#pragma unroll
        for (int ks = 0; ks < 8; ks++) {
            int k0 = ks * 16;
            uint32_t ah[4][4], al[4][4], bf[2][4];
#pragma unroll
            for (int mf = 0; mf < 4; mf++) {
                uint32_t off = (uint32_t)(((m0 + mf * 16 + arow) * LDT + k0 + acol8) * 2);
                ldm_x4(ah[mf], sAh_u + off);
                ldm_x4(al[mf], sAl_u + off);
            }
#pragma unroll
            for (int nh = 0; nh < 2; nh++) {
                uint32_t off = (uint32_t)(((n0 + nh * 16 + brow) * LDT + k0 + bcol) * 2);
                ldm_x4(bf[nh], sB_u + off);
            }
#pragma unroll
            for (int mf = 0; mf < 4; mf++)
#pragma unroll
                for (int nf = 0; nf < 4; nf++) {
                    const uint32_t* bp = &bf[nf >> 1][(nf & 1) * 2];
                    mma16816(acc[mf][nf], ah[mf], bp);
                    mma16816(acc[mf][nf], al[mf], bp);
                }
        }

        // fragment-local dot with head
        float part[4][2];
#pragma unroll
        for (int mf = 0; mf < 4; mf++) { part[mf][0] = 0.f; part[mf][1] = 0.f; }
#pragma unroll
        for (int mf = 0; mf < 4; mf++) {
            int ra = m0 + mf * 16 + r01;
#pragma unroll
            for (int nf = 0; nf < 4; nf++) {
                int col = n0 + nf * 8 + cql;
                float2 h0 = *(float2*)&Hs[ra * LDH + col];
                float2 h1 = *(float2*)&Hs[(ra + 8) * LDH + col];
                part[mf][0] += acc[mf][nf][0] * h0.x + acc[mf][nf][1] * h0.y;
                part[mf][1] += acc[mf][nf][2] * h1.x + acc[mf][nf][3] * h1.y;
            }
        }
#pragma unroll
        for (int mf = 0; mf < 4; mf++) {
#pragma unroll
            for (int hh = 0; hh < 2; hh++) {
                part[mf][hh] += __shfl_xor_sync(0xffffffffu, part[mf][hh], 1);
                part[mf][hh] += __shfl_xor_sync(0xffffffffu, part[mf][hh], 2);
            }
        }
        if ((l & 3) == 0) {
#pragma unroll
            for (int mf = 0; mf < 4; mf++) {
                atomicAdd(&out_s[m0 + mf * 16 + r01], part[mf][0]);
                atomicAdd(&out_s[m0 + mf * 16 + r01 + 8], part[mf][1]);
            }
        }
        __syncthreads();
        if (t < 128)
            out[(long)(tile * 128 + t) * NREL + r] = out_s[t];
    }
}

// ==================== launch ================================================
extern "C" void kernel_launch(void* const* d_in, const int* in_sizes, int n_in,
                              void* d_out, int out_size) {
    const float* init_emb = (const float*)d_in[0];
    const float* W1       = (const float*)d_in[1];
    const float* b1       = (const float*)d_in[2];
    const float* W2       = (const float*)d_in[3];
    const float* b2       = (const float*)d_in[4];
    const float* Rp       = (const float*)d_in[5];
    const float* Mp       = (const float*)d_in[6];
    const int*   head     = (const int*)d_in[7];
    const int*   tail     = (const int*)d_in[8];
    const int*   ei       = (const int*)d_in[9];
    float* out = (float*)d_out;

    const int* src = ei;
    const int* dst = ei + NEDGES;

    float *p_h, *p_x1, *p_x2, *p_dinv, *p_T, *p_head;
    __half *p_WTh, *p_Rh, *p_Sh, *p_thi, *p_tlo;
    int *p_cnt, *p_rowptr, *p_cur, *p_col;
    cudaGetSymbolAddress((void**)&p_h, g_h);
    cudaGetSymbolAddress((void**)&p_x1, g_x1);
    cudaGetSymbolAddress((void**)&p_x2, g_x2);
    cudaGetSymbolAddress((void**)&p_dinv, g_dinv);
    cudaGetSymbolAddress((void**)&p_cnt, g_cnt);
    cudaGetSymbolAddress((void**)&p_rowptr, g_rowptr);
    cudaGetSymbolAddress((void**)&p_cur, g_cur);
    cudaGetSymbolAddress((void**)&p_col, g_col);
    cudaGetSymbolAddress((void**)&p_T, g_T);
    cudaGetSymbolAddress((void**)&p_WTh, g_WTh);
    cudaGetSymbolAddress((void**)&p_Rh, g_Rh);
    cudaGetSymbolAddress((void**)&p_Sh, g_Sh);
    cudaGetSymbolAddress((void**)&p_head, g_head);
    cudaGetSymbolAddress((void**)&p_thi, g_thi);
    cudaGetSymbolAddress((void**)&p_tlo, g_tlo);

    const int GEMM_SMEM  = 3 * 128 * LDT * 2;                       // 104448
    const int SCORE_SMEM = GEMM_SMEM + 128 * LDH * 4 + 128 * 4;     // 172544
    cudaFuncSetAttribute(gemm_mma,  cudaFuncAttributeMaxDynamicSharedMemorySize, GEMM_SMEM);
    cudaFuncSetAttribute(score_mma, cudaFuncAttributeMaxDynamicSharedMemorySize, SCORE_SMEM);

    // ---- fork/join streams for capture-parallel branches ----
    cudaStream_t sB, sC;
    cudaStreamCreateWithFlags(&sB, cudaStreamNonBlocking);
    cudaStreamCreateWithFlags(&sC, cudaStreamNonBlocking);
    cudaEvent_t evRoot, evW, evCSR, evS;
    cudaEventCreateWithFlags(&evRoot, cudaEventDisableTiming);
    cudaEventCreateWithFlags(&evW,    cudaEventDisableTiming);
    cudaEventCreateWithFlags(&evCSR,  cudaEventDisableTiming);
    cudaEventCreateWithFlags(&evS,    cudaEventDisableTiming);

    cudaEventRecord(evRoot, 0);

    // --- branch B: CSR build (independent of node chain until agg1) ---
    cudaStreamWaitEvent(sB, evRoot, 0);
    zero_cnt_kernel<<<(NNODES + 255) / 256, 256, 0, sB>>>(p_cnt, NNODES);
    count_kernel<<<(NEDGES / 4 + 255) / 256, 256, 0, sB>>>(
        (const int4*)dst, p_cnt, NEDGES / 4);
    scan_kernel<<<1, 1024, 0, sB>>>(p_cnt, p_rowptr, p_cur, p_dinv, NNODES);
    fill_kernel<<<(NEDGES / 4 + 255) / 256, 256, 0, sB>>>(
        (const int4*)src, (const int4*)dst, p_cur, p_col, NEDGES / 4);
    cudaEventRecord(evCSR, sB);

    // --- main: weight prep (needed by gemm1 and by branch C's T-GEMM) ---
    prepW_kernel<<<3, 128>>>(W1, W2, Mp, p_WTh);
    cudaEventRecord(evW, 0);

    // --- branch C: relation prep + S precompute ---
    cudaStreamWaitEvent(sC, evRoot, 0);
    prepR_kernel<<<(NREL * 16384 / 8 + 255) / 256, 256, 0, sC>>>(Rp, p_Rh);
    cudaStreamWaitEvent(sC, evW, 0);
    gemm_mma<<<dim3(1, NREL), 256, GEMM_SMEM, sC>>>(
        Rp, 16384, p_WTh + 2 * 16384, 0,
        p_T, 16384, nullptr, 0, 128);
    gemm_mma<<<dim3(1, NREL), 256, GEMM_SMEM, sC>>>(
        p_T, 16384, p_Rh, 16384,
        nullptr, 0, p_Sh, 16384, 128);
    cudaEventRecord(evS, sC);

    int ntiles = (NNODES + 127) / 128;  // 391
    int agg_blocks = (NNODES * 32 + 255) / 256;

    // --- main chain ---
    gemm_mma<<<dim3(ntiles, 1), 256, GEMM_SMEM>>>(
        init_emb, 0, p_WTh, 0, p_h, 0,
        nullptr, 0, NNODES);
    cudaStreamWaitEvent(0, evCSR, 0);
    agg_kernel<<<agg_blocks, 256>>>(p_h, p_rowptr, p_col, p_dinv, b1, p_x1, NNODES);
    gemm_mma<<<dim3(ntiles, 1), 256, GEMM_SMEM>>>(
        p_x1, 0, p_WTh + 16384, 0, p_h, 0,
        nullptr, 0, NNODES);
    agg_kernel<<<agg_blocks, 256>>>(p_h, p_rowptr, p_col, p_dinv, b2, p_x2, NNODES);

    gather_kernel<<<NBATCH / 128, 128>>>(p_x2, head, tail, p_head, p_thi, p_tlo);

    cudaStreamWaitEvent(0, evS, 0);
    score_mma<<<dim3(NBATCH / 128, NREL / 2), 256, SCORE_SMEM>>>(
        p_thi, p_tlo, p_Sh, p_head, out);

    cudaStreamDestroy(sB);
    cudaStreamDestroy(sC);
    cudaEventDestroy(evRoot);
    cudaEventDestroy(evW);
    cudaEventDestroy(evCSR);
    cudaEventDestroy(evS);
}

// round 7
// speedup vs baseline: 2.3453x; 1.1213x over previous
#include <cuda_runtime.h>
#include <cuda_fp16.h>
#include <cstdint>
#include <math.h>

#define NNODES 50000
#define NEDGES 800000
#define DIM    128
#define NREL   86
#define NBATCH 2048
#define LDT    136   // fp16 smem stride (elems)
#define LDH    132   // fp32 head smem stride (elems)

// ---------------- scratch (device globals; no allocation allowed) ------------
__device__ float g_h  [NNODES * DIM];
__device__ float g_x1 [NNODES * DIM];
__device__ float g_dinv[NNODES];
__device__ int   g_cnt [NNODES];
__device__ int   g_rowptr[NNODES + 1];
__device__ int   g_cur [NNODES];
__device__ int   g_col [NEDGES];
__device__ float g_T   [NREL * DIM * DIM];
__device__ __half g_WTh[3 * DIM * DIM];     // W1^T, W2^T, M^T  (fp16 hi)
__device__ __half g_WTl[3 * DIM * DIM];     // lo terms (used for M)
__device__ __half g_Rh [NREL * DIM * DIM];  // R hi ([f][k] layout)
__device__ __half g_Rl [NREL * DIM * DIM];  // R lo
__device__ __half g_Sh [NREL * DIM * DIM];  // S (single fp16)
__device__ float g_head[NBATCH * DIM];
__device__ __half g_thi[NBATCH * DIM];      // tail hi (exact fp16 split)
__device__ __half g_tlo[NBATCH * DIM];      // tail lo

// ==================== helpers ===============================================
__device__ __forceinline__ uint32_t smem_u32(const void* p) {
    uint32_t a;
    asm("{ .reg .u64 t; cvta.to.shared.u64 t, %1; cvt.u32.u64 %0, t; }"
        : "=r"(a) : "l"(p));
    return a;
}

__device__ __forceinline__ void ldm_x4(uint32_t* r, uint32_t addr) {
    asm volatile("ldmatrix.sync.aligned.m8n8.x4.shared.b16 {%0,%1,%2,%3}, [%4];"
                 : "=r"(r[0]), "=r"(r[1]), "=r"(r[2]), "=r"(r[3]) : "r"(addr));
}

__device__ __forceinline__ void mma16816(float* d, const uint32_t* a,
                                         const uint32_t* b) {
    asm volatile(
        "mma.sync.aligned.m16n8k16.row.col.f32.f16.f16.f32 "
        "{%0,%1,%2,%3}, {%4,%5,%6,%7}, {%8,%9}, {%0,%1,%2,%3};"
        : "+f"(d[0]), "+f"(d[1]), "+f"(d[2]), "+f"(d[3])
        : "r"(a[0]), "r"(a[1]), "r"(a[2]), "r"(a[3]), "r"(b[0]), "r"(b[1]));
}

// split two fp32 -> packed fp16x2 hi + lo (exact 2-term repr)
__device__ __forceinline__ void hcvt2(float a, float b, uint32_t& hi, uint32_t& lo) {
    __half2 h = __floats2half2_rn(a, b);
    float ra = a - __half2float(__low2half(h));
    float rb = b - __half2float(__high2half(h));
    __half2 l = __floats2half2_rn(ra, rb);
    hi = *(uint32_t*)&h;
    lo = *(uint32_t*)&l;
}
__device__ __forceinline__ void hcvt8(const float* v, uint4& hi, uint4& lo) {
    uint32_t h[4], l[4];
#pragma unroll
    for (int i = 0; i < 4; i++) hcvt2(v[2 * i], v[2 * i + 1], h[i], l[i]);
    hi = make_uint4(h[0], h[1], h[2], h[3]);
    lo = make_uint4(l[0], l[1], l[2], l[3]);
}

// ==================== CSR build =============================================
__global__ void zero_cnt_kernel(int* cnt, int n) {
    int i = blockIdx.x * blockDim.x + threadIdx.x;
    if (i < n) cnt[i] = 0;
}
__global__ void count_kernel(const int4* __restrict__ dst4, int* cnt, int e4) {
    int i = blockIdx.x * blockDim.x + threadIdx.x;
    if (i < e4) {
        int4 d = dst4[i];
        atomicAdd(&cnt[d.x], 1);
        atomicAdd(&cnt[d.y], 1);
        atomicAdd(&cnt[d.z], 1);
        atomicAdd(&cnt[d.w], 1);
    }
}
__global__ void scan_kernel(const int* __restrict__ cnt, int* rowptr, int* cur,
                            float* dinv, int n) {
    __shared__ int ssum[1024];
    int t = threadIdx.x;
    int chunk = (n + 1023) / 1024;
    int beg = t * chunk, end = min(beg + chunk, n);
    int s = 0;
    for (int i = beg; i < end; i++) s += cnt[i];
    ssum[t] = s;
    __syncthreads();
    for (int off = 1; off < 1024; off <<= 1) {
        int v = (t >= off) ? ssum[t - off] : 0;
        __syncthreads();
        ssum[t] += v;
        __syncthreads();
    }
    int base = (t == 0) ? 0 : ssum[t - 1];
    for (int i = beg; i < end; i++) {
        rowptr[i] = base; cur[i] = base;
        dinv[i] = rsqrtf((float)(cnt[i] + 1));
        base += cnt[i];
    }
    if (t == 1023) rowptr[n] = ssum[1023];
}
__global__ void fill_kernel(const int4* __restrict__ src4,
                            const int4* __restrict__ dst4,
                            int* cur, int* col, int e4) {
    int i = blockIdx.x * blockDim.x + threadIdx.x;
    if (i < e4) {
        int4 d = dst4[i];
        int4 s = src4[i];
        col[atomicAdd(&cur[d.x], 1)] = s.x;
        col[atomicAdd(&cur[d.y], 1)] = s.y;
        col[atomicAdd(&cur[d.z], 1)] = s.z;
        col[atomicAdd(&cur[d.w], 1)] = s.w;
    }
}

// ==================== operand prep ==========================================
// transpose W1, W2, M into [n][k] layout, fp16 hi + lo
__global__ void prepW_kernel(const float* __restrict__ W1,
                             const float* __restrict__ W2,
                             const float* __restrict__ M,
                             __half* outH, __half* outL) {
    int mat = blockIdx.x, t = threadIdx.x; // t = output row n
    const float* src = (mat == 0) ? W1 : (mat == 1) ? W2 : M;
    float v[8];
    for (int g = 0; g < 16; g++) {
#pragma unroll
        for (int j = 0; j < 8; j++) v[j] = src[(g * 8 + j) * 128 + t];
        uint4 hi, lo; hcvt8(v, hi, lo);
        long off = (long)mat * 16384 + t * 128 + g * 8;
        *(uint4*)&outH[off] = hi;
        *(uint4*)&outL[off] = lo;
    }
}

// elementwise fp16 split of relation_param (R stays [f][k] layout)
__global__ void prepR_kernel(const float* __restrict__ R,
                             __half* outH, __half* outL) {
    long i = (long)(blockIdx.x * blockDim.x + threadIdx.x) * 8;
    if (i >= (long)NREL * 16384) return;
    float v[8];
    float4 a0 = *(const float4*)&R[i];
    float4 a1 = *(const float4*)&R[i + 4];
    v[0]=a0.x; v[1]=a0.y; v[2]=a0.z; v[3]=a0.w;
    v[4]=a1.x; v[5]=a1.y; v[6]=a1.z; v[7]=a1.w;
    uint4 hi, lo; hcvt8(v, hi, lo);
    *(uint4*)&outH[i] = hi;
    *(uint4*)&outL[i] = lo;
}

// ==================== HMMA GEMM (fp16, 2 or 3 pass) =========================
// C[rows,128] = A[rows,128] @ Bmath, smem B holds Bs[n][k] fp16
// (Bmath[k][n] = Bs[n][k]).  A fp32 -> exact fp16 hi/lo split in-block.
// Blo != nullptr -> 3rd pass Ahi*Blo for near-fp32 B accuracy.
// Output: fp32 C  OR  single-fp16 row-major (So).
__global__ void __launch_bounds__(256)
gemm_mma(const float* __restrict__ A, long strideA,
         const __half* __restrict__ Bhi, const __half* __restrict__ Blo,
         long strideB,
         float* __restrict__ C, long strideC,
         __half* So, long strideS,
         int rows) {
    extern __shared__ char smem[];
    __half* sAh = (__half*)smem;
    __half* sAl = sAh + 128 * LDT;
    __half* sBh = sAl + 128 * LDT;
    __half* sBl = sBh + 128 * LDT;   // only valid when Blo != nullptr (4-tile launch)

    int t = threadIdx.x, wid = t >> 5, l = t & 31;
    int batch = blockIdx.y;
    const float* Ab = A + (long)batch * strideA;
    const __half* Bhb = Bhi + (long)batch * strideB;
    int row0 = blockIdx.x * 128;

    // ---- stage A (fp32 -> fp16 split) and B into padded smem ----
    {
        int rr = t >> 1, hc = (t & 1) * 64;
        int grow = row0 + rr;
        const float* ar = Ab + (long)grow * 128 + hc;
        float v[8];
#pragma unroll
        for (int g = 0; g < 8; g++) {
            if (grow < rows) {
                float4 a0 = *(const float4*)&ar[g * 8];
                float4 a1 = *(const float4*)&ar[g * 8 + 4];
                v[0]=a0.x; v[1]=a0.y; v[2]=a0.z; v[3]=a0.w;
                v[4]=a1.x; v[5]=a1.y; v[6]=a1.z; v[7]=a1.w;
            } else {
#pragma unroll
                for (int j = 0; j < 8; j++) v[j] = 0.f;
            }
            uint4 hi, lo; hcvt8(v, hi, lo);
            int so = rr * LDT + hc + g * 8;
            *(uint4*)&sAh[so] = hi;
            *(uint4*)&sAl[so] = lo;
        }
#pragma unroll
        for (int g = 0; g < 8; g++) {
            long goff = (long)rr * 128 + hc + g * 8;
            int so = rr * LDT + hc + g * 8;
            *(uint4*)&sBh[so] = *(const uint4*)&Bhb[goff];
        }
        if (Blo) {
            const __half* Blb = Blo + (long)batch * strideB;
#pragma unroll
            for (int g = 0; g < 8; g++) {
                long goff = (long)rr * 128 + hc + g * 8;
                int so = rr * LDT + hc + g * 8;
                *(uint4*)&sBl[so] = *(const uint4*)&Blb[goff];
            }
        }
    }
    __syncthreads();

    uint32_t sAh_u = smem_u32(sAh), sAl_u = smem_u32(sAl);
    uint32_t sBh_u = smem_u32(sBh), sBl_u = smem_u32(sBl);

    int wm = wid >> 2, wn = wid & 3;
    int m0 = wm * 64, n0 = wn * 32;
    int arow = l & 15, acol8 = (l >> 4) * 8;
    int brow = (l & 7) + (l >> 4) * 8, bcol = ((l >> 3) & 1) * 8;

    float acc[4][4][4];
#pragma unroll
    for (int mf = 0; mf < 4; mf++)
#pragma unroll
        for (int nf = 0; nf < 4; nf++)
#pragma unroll
            for (int c = 0; c < 4; c++) acc[mf][nf][c] = 0.f;

#pragma unroll
    for (int ks = 0; ks < 8; ks++) {
        int k0 = ks * 16;
        uint32_t ah[4][4], al[4][4], bh[2][4], bl[2][4];
#pragma unroll
        for (int mf = 0; mf < 4; mf++) {
            uint32_t off = (uint32_t)(((m0 + mf * 16 + arow) * LDT + k0 + acol8) * 2);
            ldm_x4(ah[mf], sAh_u + off);
            ldm_x4(al[mf], sAl_u + off);
        }
#pragma unroll
        for (int nh = 0; nh < 2; nh++) {
            uint32_t off = (uint32_t)(((n0 + nh * 16 + brow) * LDT + k0 + bcol) * 2);
            ldm_x4(bh[nh], sBh_u + off);
            if (Blo) ldm_x4(bl[nh], sBl_u + off);
        }
#pragma unroll
        for (int mf = 0; mf < 4; mf++)
#pragma unroll
            for (int nf = 0; nf < 4; nf++) {
                const uint32_t* bp = &bh[nf >> 1][(nf & 1) * 2];
                mma16816(acc[mf][nf], ah[mf], bp);
                mma16816(acc[mf][nf], al[mf], bp);
                if (Blo) {
                    const uint32_t* blp = &bl[nf >> 1][(nf & 1) * 2];
                    mma16816(acc[mf][nf], ah[mf], blp);
                }
            }
    }

    // ---- epilogue ----
    int r01 = l >> 2, cql = (l & 3) * 2;
    if (So) {
        __half* oh = So + (long)batch * strideS;
#pragma unroll
        for (int mf = 0; mf < 4; mf++) {
            int ra = m0 + mf * 16 + r01, rb = ra + 8;
#pragma unroll
            for (int nf = 0; nf < 4; nf++) {
                int col = n0 + nf * 8 + cql;
                __half2 p0 = __floats2half2_rn(acc[mf][nf][0], acc[mf][nf][1]);
                __half2 p1 = __floats2half2_rn(acc[mf][nf][2], acc[mf][nf][3]);
                *(uint32_t*)&oh[ra * 128 + col] = *(uint32_t*)&p0;
                *(uint32_t*)&oh[rb * 128 + col] = *(uint32_t*)&p1;
            }
        }
    } else {
        float* Cb = C + (long)batch * strideC;
#pragma unroll
        for (int mf = 0; mf < 4; mf++) {
            int ga = row0 + m0 + mf * 16 + r01, gb = ga + 8;
#pragma unroll
            for (int nf = 0; nf < 4; nf++) {
                int col = n0 + nf * 8 + cql;
                if (ga < rows) {
                    float2 v = make_float2(acc[mf][nf][0], acc[mf][nf][1]);
                    *(float2*)&Cb[(long)ga * 128 + col] = v;
                }
                if (gb < rows) {
                    float2 v = make_float2(acc[mf][nf][2], acc[mf][nf][3]);
                    *(float2*)&Cb[(long)gb * 128 + col] = v;
                }
            }
        }
    }
}

// ==================== aggregation (full, layer 1) ===========================
// out[d] = dinv[d] * ( sum_s dinv[s]*h[s] + dinv[d]*h[d] ) + b
__global__ void agg_kernel(const float* __restrict__ h,
                           const int* __restrict__ rowptr,
                           const int* __restrict__ col,
                           const float* __restrict__ dinv,
                           const float* __restrict__ bias,
                           float* __restrict__ out, int n) {
    int warp = (blockIdx.x * blockDim.x + threadIdx.x) >> 5;
    int lane = threadIdx.x & 31;
    if (warp >= n) return;
    int beg = rowptr[warp], end = rowptr[warp + 1];
    float dv = dinv[warp];

    float4 self = *(const float4*)&h[(long)warp * 128 + lane * 4];
    float4 acc = make_float4(dv * self.x, dv * self.y, dv * self.z, dv * self.w);

    int e = beg;
    for (; e + 4 <= end; e += 4) {
        int s0 = col[e], s1 = col[e + 1], s2 = col[e + 2], s3 = col[e + 3];
        float w0 = dinv[s0], w1 = dinv[s1], w2 = dinv[s2], w3 = dinv[s3];
        float4 v0 = *(const float4*)&h[(long)s0 * 128 + lane * 4];
        float4 v1 = *(const float4*)&h[(long)s1 * 128 + lane * 4];
        float4 v2 = *(const float4*)&h[(long)s2 * 128 + lane * 4];
        float4 v3 = *(const float4*)&h[(long)s3 * 128 + lane * 4];
        acc.x = fmaf(w0, v0.x, fmaf(w1, v1.x, fmaf(w2, v2.x, fmaf(w3, v3.x, acc.x))));
        acc.y = fmaf(w0, v0.y, fmaf(w1, v1.y, fmaf(w2, v2.y, fmaf(w3, v3.y, acc.y))));
        acc.z = fmaf(w0, v0.z, fmaf(w1, v1.z, fmaf(w2, v2.z, fmaf(w3, v3.z, acc.z))));
        acc.w = fmaf(w0, v0.w, fmaf(w1, v1.w, fmaf(w2, v2.w, fmaf(w3, v3.w, acc.w))));
    }
    for (; e < end; e++) {
        int s = col[e];
        float w = dinv[s];
        float4 v = *(const float4*)&h[(long)s * 128 + lane * 4];
        acc.x = fmaf(w, v.x, acc.x);
        acc.y = fmaf(w, v.y, acc.y);
        acc.z = fmaf(w, v.z, acc.z);
        acc.w = fmaf(w, v.w, acc.w);
    }
    float4 bb = *(const float4*)&bias[lane * 4];
    *(float4*)&out[(long)warp * 128 + lane * 4] =
        make_float4(acc.x * dv + bb.x, acc.y * dv + bb.y,
                    acc.z * dv + bb.z, acc.w * dv + bb.w);
}

// ==================== batch-only aggregation (layer 2 + gather fused) =======
// One warp per (batch, head|tail): aggregate that node's x2 row from h2 and
// write straight into the scorer's operand buffers.
__global__ void agg_batch_kernel(const float* __restrict__ h,
                                 const int* __restrict__ rowptr,
                                 const int* __restrict__ col,
                                 const float* __restrict__ dinv,
                                 const float* __restrict__ bias,
                                 const int* __restrict__ head,
                                 const int* __restrict__ tail,
                                 float* __restrict__ Hg,
                                 __half* __restrict__ Thi,
                                 __half* __restrict__ Tlo) {
    int gw = (blockIdx.x * blockDim.x + threadIdx.x) >> 5;
    int lane = threadIdx.x & 31;
    if (gw >= 2 * NBATCH) return;
    int b = gw >> 1, which = gw & 1;
    int node = which ? tail[b] : head[b];

    int beg = rowptr[node], end = rowptr[node + 1];
    float dv = dinv[node];

    float4 self = *(const float4*)&h[(long)node * 128 + lane * 4];
    float4 acc = make_float4(dv * self.x, dv * self.y, dv * self.z, dv * self.w);

    int e = beg;
    for (; e + 4 <= end; e += 4) {
        int s0 = col[e], s1 = col[e + 1], s2 = col[e + 2], s3 = col[e + 3];
        float w0 = dinv[s0], w1 = dinv[s1], w2 = dinv[s2], w3 = dinv[s3];
        float4 v0 = *(const float4*)&h[(long)s0 * 128 + lane * 4];
        float4 v1 = *(const float4*)&h[(long)s1 * 128 + lane * 4];
        float4 v2 = *(const float4*)&h[(long)s2 * 128 + lane * 4];
        float4 v3 = *(const float4*)&h[(long)s3 * 128 + lane * 4];
        acc.x = fmaf(w0, v0.x, fmaf(w1, v1.x, fmaf(w2, v2.x, fmaf(w3, v3.x, acc.x))));
        acc.y = fmaf(w0, v0.y, fmaf(w1, v1.y, fmaf(w2, v2.y, fmaf(w3, v3.y, acc.y))));
        acc.z = fmaf(w0, v0.z, fmaf(w1, v1.z, fmaf(w2, v2.z, fmaf(w3, v3.z, acc.z))));
        acc.w = fmaf(w0, v0.w, fmaf(w1, v1.w, fmaf(w2, v2.w, fmaf(w3, v3.w, acc.w))));
    }
    for (; e < end; e++) {
        int s = col[e];
        float w = dinv[s];
        float4 v = *(const float4*)&h[(long)s * 128 + lane * 4];
        acc.x = fmaf(w, v.x, acc.x);
        acc.y = fmaf(w, v.y, acc.y);
        acc.z = fmaf(w, v.z, acc.z);
        acc.w = fmaf(w, v.w, acc.w);
    }
    float4 bb = *(const float4*)&bias[lane * 4];
    float4 res = make_float4(acc.x * dv + bb.x, acc.y * dv + bb.y,
                             acc.z * dv + bb.z, acc.w * dv + bb.w);
    long off = (long)b * 128 + lane * 4;
    if (!which) {
        *(float4*)&Hg[off] = res;
    } else {
        uint32_t h0, l0, h1, l1;
        hcvt2(res.x, res.y, h0, l0);
        hcvt2(res.z, res.w, h1, l1);
        *(uint32_t*)&Thi[off] = h0;
        *(uint32_t*)&Thi[off + 2] = h1;
        *(uint32_t*)&Tlo[off] = l0;
        *(uint32_t*)&Tlo[off + 2] = l1;
    }
}

// ==================== scorer ================================================
// block = (batch tile of 128) x (pair of relations).
// P2[b,e] = sum_f tail[b,f] * S_r[e,f]  (HMMA fp16 2-pass, tail exact split)
// out[b,r] = sum_e P2[b,e] * head[b,e]  (fp32, fragment-local)
__global__ void __launch_bounds__(256)
score_mma(const __half* __restrict__ Thi,
          const __half* __restrict__ Tlo,
          const __half* __restrict__ Sh,
          const float* __restrict__ Hg, float* __restrict__ out) {
    extern __shared__ char smem[];
    __half* sAh = (__half*)smem;
    __half* sAl = sAh + 128 * LDT;
    __half* sB  = sAl + 128 * LDT;
    float* Hs = (float*)(sB + 128 * LDT);        // [128][LDH]
    float* out_s = Hs + 128 * LDH;               // [128]

    int t = threadIdx.x, wid = t >> 5, l = t & 31;
    int tile = blockIdx.x, rpair = blockIdx.y;
    int rr = t >> 1, hc = (t & 1) * 64;

    // stage tail tile + head tile
    {
        long base = (long)(tile * 128 + rr) * 128 + hc;
#pragma unroll
        for (int g = 0; g < 8; g++) {
            int so = rr * LDT + hc + g * 8;
            *(uint4*)&sAh[so] = *(const uint4*)&Thi[base + g * 8];
            *(uint4*)&sAl[so] = *(const uint4*)&Tlo[base + g * 8];
        }
        const float* hr = Hg + (long)(tile * 128 + rr) * 128 + hc;
#pragma unroll
        for (int g = 0; g < 8; g++) {
            float4 v0 = *(const float4*)&hr[g * 8];
            float4 v1 = *(const float4*)&hr[g * 8 + 4];
            int so = rr * LDH + hc + g * 8;
            *(float4*)&Hs[so] = v0;
            *(float4*)&Hs[so + 4] = v1;
        }
    }

    uint32_t sAh_u = smem_u32(sAh), sAl_u = smem_u32(sAl);
    uint32_t sB_u = smem_u32(sB);

    int wm = wid >> 2, wn = wid & 3;
    int m0 = wm * 64, n0 = wn * 32;
    int arow = l & 15, acol8 = (l >> 4) * 8;
    int brow = (l & 7) + (l >> 4) * 8, bcol = ((l >> 3) & 1) * 8;
    int r01 = l >> 2, cql = (l & 3) * 2;

    for (int i = 0; i < 2; i++) {
        int r = rpair * 2 + i;
        __syncthreads();   // protect B smem + out_s from prior readers
        // stage S_r (single fp16)
        {
            long base = (long)r * 16384 + rr * 128 + hc;
#pragma unroll
            for (int g = 0; g < 8; g++) {
                int so = rr * LDT + hc + g * 8;
                *(uint4*)&sB[so] = *(const uint4*)&Sh[base + g * 8];
            }
        }
        if (t < 128) out_s[t] = 0.f;
        __syncthreads();

        float acc[4][4][4];
#pragma unroll
        for (int mf = 0; mf < 4; mf++)
#pragma unroll
            for (int nf = 0; nf < 4; nf++)
#pragma unroll
                for (int c = 0; c < 4; c++) acc[mf][nf][c] = 0.f;

#pragma unroll
        for (int ks = 0; ks < 8; ks++) {
            int k0 = ks * 16;
            uint32_t ah[4][4], al[4][4], bf[2][4];
#pragma unroll
            for (int mf = 0; mf < 4; mf++) {
                uint32_t off = (uint32_t)(((m0 + mf * 16 + arow) * LDT + k0 + acol8) * 2);
                ldm_x4(ah[mf], sAh_u + off);
                ldm_x4(al[mf], sAl_u + off);
            }
#pragma unroll
            for (int nh = 0; nh < 2; nh++) {
                uint32_t off = (uint32_t)(((n0 + nh * 16 + brow) * LDT + k0 + bcol) * 2);
                ldm_x4(bf[nh], sB_u + off);
            }
#pragma unroll
            for (int mf = 0; mf < 4; mf++)
#pragma unroll
                for (int nf = 0; nf < 4; nf++) {
                    const uint32_t* bp = &bf[nf >> 1][(nf & 1) * 2];
                    mma16816(acc[mf][nf], ah[mf], bp);
                    mma16816(acc[mf][nf], al[mf], bp);
                }
        }

        // fragment-local dot with head
        float part[4][2];
#pragma unroll
        for (int mf = 0; mf < 4; mf++) { part[mf][0] = 0.f; part[mf][1] = 0.f; }
#pragma unroll
        for (int mf = 0; mf < 4; mf++) {
            int ra = m0 + mf * 16 + r01;
#pragma unroll
            for (int nf = 0; nf < 4; nf++) {
                int col = n0 + nf * 8 + cql;
                float2 h0 = *(float2*)&Hs[ra * LDH + col];
                float2 h1 = *(float2*)&Hs[(ra + 8) * LDH + col];
                part[mf][0] += acc[mf][nf][0] * h0.x + acc[mf][nf][1] * h0.y;
                part[mf][1] += acc[mf][nf][2] * h1.x + acc[mf][nf][3] * h1.y;
            }
        }
#pragma unroll
        for (int mf = 0; mf < 4; mf++) {
#pragma unroll
            for (int hh = 0; hh < 2; hh++) {
                part[mf][hh] += __shfl_xor_sync(0xffffffffu, part[mf][hh], 1);
                part[mf][hh] += __shfl_xor_sync(0xffffffffu, part[mf][hh], 2);
            }
        }
        if ((l & 3) == 0) {
#pragma unroll
            for (int mf = 0; mf < 4; mf++) {
                atomicAdd(&out_s[m0 + mf * 16 + r01], part[mf][0]);
                atomicAdd(&out_s[m0 + mf * 16 + r01 + 8], part[mf][1]);
            }
        }
        __syncthreads();
        if (t < 128)
            out[(long)(tile * 128 + t) * NREL + r] = out_s[t];
    }
}

// ==================== launch ================================================
extern "C" void kernel_launch(void* const* d_in, const int* in_sizes, int n_in,
                              void* d_out, int out_size) {
    const float* init_emb = (const float*)d_in[0];
    const float* W1       = (const float*)d_in[1];
    const float* b1       = (const float*)d_in[2];
    const float* W2       = (const float*)d_in[3];
    const float* b2       = (const float*)d_in[4];
    const float* Rp       = (const float*)d_in[5];
    const float* Mp       = (const float*)d_in[6];
    const int*   head     = (const int*)d_in[7];
    const int*   tail     = (const int*)d_in[8];
    const int*   ei       = (const int*)d_in[9];
    float* out = (float*)d_out;

    const int* src = ei;
    const int* dst = ei + NEDGES;

    float *p_h, *p_x1, *p_dinv, *p_T, *p_head;
    __half *p_WTh, *p_WTl, *p_Rh, *p_Rl, *p_Sh, *p_thi, *p_tlo;
    int *p_cnt, *p_rowptr, *p_cur, *p_col;
    cudaGetSymbolAddress((void**)&p_h, g_h);
    cudaGetSymbolAddress((void**)&p_x1, g_x1);
    cudaGetSymbolAddress((void**)&p_dinv, g_dinv);
    cudaGetSymbolAddress((void**)&p_cnt, g_cnt);
    cudaGetSymbolAddress((void**)&p_rowptr, g_rowptr);
    cudaGetSymbolAddress((void**)&p_cur, g_cur);
    cudaGetSymbolAddress((void**)&p_col, g_col);
    cudaGetSymbolAddress((void**)&p_T, g_T);
    cudaGetSymbolAddress((void**)&p_WTh, g_WTh);
    cudaGetSymbolAddress((void**)&p_WTl, g_WTl);
    cudaGetSymbolAddress((void**)&p_Rh, g_Rh);
    cudaGetSymbolAddress((void**)&p_Rl, g_Rl);
    cudaGetSymbolAddress((void**)&p_Sh, g_Sh);
    cudaGetSymbolAddress((void**)&p_head, g_head);
    cudaGetSymbolAddress((void**)&p_thi, g_thi);
    cudaGetSymbolAddress((void**)&p_tlo, g_tlo);

    const int GEMM_SMEM3 = 3 * 128 * LDT * 2;                        // 104448
    const int GEMM_SMEM4 = 4 * 128 * LDT * 2;                        // 139264
    const int SCORE_SMEM = GEMM_SMEM3 + 128 * LDH * 4 + 128 * 4;     // 172544
    cudaFuncSetAttribute(gemm_mma,  cudaFuncAttributeMaxDynamicSharedMemorySize, GEMM_SMEM4);
    cudaFuncSetAttribute(score_mma, cudaFuncAttributeMaxDynamicSharedMemorySize, SCORE_SMEM);

    // ---- fork/join streams for capture-parallel branches ----
    cudaStream_t sB, sC;
    cudaStreamCreateWithFlags(&sB, cudaStreamNonBlocking);
    cudaStreamCreateWithFlags(&sC, cudaStreamNonBlocking);
    cudaEvent_t evRoot, evW, evCSR, evS;
    cudaEventCreateWithFlags(&evRoot, cudaEventDisableTiming);
    cudaEventCreateWithFlags(&evW,    cudaEventDisableTiming);
    cudaEventCreateWithFlags(&evCSR,  cudaEventDisableTiming);
    cudaEventCreateWithFlags(&evS,    cudaEventDisableTiming);

    cudaEventRecord(evRoot, 0);

    // --- branch B: CSR build (independent of node chain until agg1) ---
    cudaStreamWaitEvent(sB, evRoot, 0);
    zero_cnt_kernel<<<(NNODES + 255) / 256, 256, 0, sB>>>(p_cnt, NNODES);
    count_kernel<<<(NEDGES / 4 + 255) / 256, 256, 0, sB>>>(
        (const int4*)dst, p_cnt, NEDGES / 4);
    scan_kernel<<<1, 1024, 0, sB>>>(p_cnt, p_rowptr, p_cur, p_dinv, NNODES);
    fill_kernel<<<(NEDGES / 4 + 255) / 256, 256, 0, sB>>>(
        (const int4*)src, (const int4*)dst, p_cur, p_col, NEDGES / 4);
    cudaEventRecord(evCSR, sB);

    // --- main: weight prep (needed by gemm1 and branch C's T-GEMM) ---
    prepW_kernel<<<3, 128>>>(W1, W2, Mp, p_WTh, p_WTl);
    cudaEventRecord(evW, 0);

    // --- branch C: relation prep + S precompute (3-pass, near-fp32) ---
    cudaStreamWaitEvent(sC, evRoot, 0);
    prepR_kernel<<<(NREL * 16384 / 8 + 255) / 256, 256, 0, sC>>>(Rp, p_Rh, p_Rl);
    cudaStreamWaitEvent(sC, evW, 0);
    gemm_mma<<<dim3(1, NREL), 256, GEMM_SMEM4, sC>>>(
        Rp, 16384, p_WTh + 2 * 16384, p_WTl + 2 * 16384, 0,
        p_T, 16384, nullptr, 0, 128);
    gemm_mma<<<dim3(1, NREL), 256, GEMM_SMEM4, sC>>>(
        p_T, 16384, p_Rh, p_Rl, 16384,
        nullptr, 0, p_Sh, 16384, 128);
    cudaEventRecord(evS, sC);

    int ntiles = (NNODES + 127) / 128;  // 391
    int agg_blocks = (NNODES * 32 + 255) / 256;

    // --- main chain ---
    gemm_mma<<<dim3(ntiles, 1), 256, GEMM_SMEM3>>>(
        init_emb, 0, p_WTh, nullptr, 0, p_h, 0,
        nullptr, 0, NNODES);
    cudaStreamWaitEvent(0, evCSR, 0);
    agg_kernel<<<agg_blocks, 256>>>(p_h, p_rowptr, p_col, p_dinv, b1, p_x1, NNODES);
    gemm_mma<<<dim3(ntiles, 1), 256, GEMM_SMEM3>>>(
        p_x1, 0, p_WTh + 16384, nullptr, 0, p_h, 0,
        nullptr, 0, NNODES);
    // fused layer-2 aggregation restricted to head/tail rows (+ gather)
    agg_batch_kernel<<<(2 * NBATCH * 32 + 255) / 256, 256>>>(
        p_h, p_rowptr, p_col, p_dinv, b2, head, tail, p_head, p_thi, p_tlo);

    cudaStreamWaitEvent(0, evS, 0);
    score_mma<<<dim3(NBATCH / 128, NREL / 2), 256, SCORE_SMEM>>>(
        p_thi, p_tlo, p_Sh, p_head, out);

    cudaStreamDestroy(sB);
    cudaStreamDestroy(sC);
    cudaEventDestroy(evRoot);
    cudaEventDestroy(evW);
    cudaEventDestroy(evCSR);
    cudaEventDestroy(evS);
}